// round 10
// baseline (speedup 1.0000x reference)
#include <cuda_runtime.h>
#include <cuda_bf16.h>
#include <cstdint>
#include <math.h>

// ---------------------------------------------------------------------------
// Problem constants
// ---------------------------------------------------------------------------
#define TSEQ  64
#define BATCH 512
#define EBD   256
#define VFD   512
#define SENSD 768
#define H0    512
#define H1    256
#define H2    64
#define C0    1280
#define C1    768
#define C2    320
#define N0    2048         // 4*H0 physical (gate-interleaved, permuted)
#define N1    1024
#define N2    256
#define NROWS (TSEQ * BATCH)

// ---------------------------------------------------------------------------
// Device-global scratch. Packed weights: per (nb, kc128) block = 32 KB:
//   [digit1: 128 n-rows x 128 k s8, SW128-swizzled 128B rows][digit2 same]
// ---------------------------------------------------------------------------
__device__ float g_W0x[SENSD * N0];   // 16 nb x 6 kc  (3MB used)
__device__ float g_W0h[H0 * N0];      // 16 nb x 4 kc  (2MB used)
__device__ float g_W1 [C1 * N1];      //  8 nb x 6 kc  (1.5MB used)
__device__ float g_W2 [C2 * N2];      //  2 nb x 3 kc  (192KB used; pad zeros)
__device__ float g_bias[3328];        // logical 4j+q, layers at 0/2048/3072
__device__ float g_cw  [3328];        // 127/colmax
__device__ float g_wsL [3328];        // colmax/127 (logical)
__device__ float g_wsP0[N0];          // colmax/127 (physical, layer0)
__device__ float g_qc [NROWS];        // 127/rowmax (sensory rows)
__device__ float g_ir [NROWS];        // rowmax/127
__device__ float g_U0 [(size_t)NROWS * N0];
__device__ float g_h0 [2 * BATCH * H0];
__device__ float g_h1 [2 * BATCH * H1];
__device__ float g_h2 [2 * BATCH * H2];

__device__ int g_bar_count;
__device__ int g_bar_gen;

// ---------------------------------------------------------------------------
// Helpers (portable PTX only: mma.sync s8 / ldmatrix / cp.async)
// ---------------------------------------------------------------------------
__device__ __forceinline__ uint32_t smem_u32(const void* p) {
    uint32_t a;
    asm("{ .reg .u64 t; cvta.to.shared.u64 t, %1; cvt.u32.u64 %0, t; }" : "=r"(a) : "l"(p));
    return a;
}
#define SWZ(o) ((o) ^ (((o) >> 3) & 0x70))

#define LDSM_X4(r0, r1, r2, r3, a) \
    asm volatile("ldmatrix.sync.aligned.m8n8.x4.shared.b16 {%0,%1,%2,%3}, [%4];" \
                 : "=r"(r0), "=r"(r1), "=r"(r2), "=r"(r3) : "r"(a))
#define LDSM_X2(r0, r1, a) \
    asm volatile("ldmatrix.sync.aligned.m8n8.x2.shared.b16 {%0,%1}, [%2];" \
                 : "=r"(r0), "=r"(r1) : "r"(a))

__device__ __forceinline__ void mma_s8(int (&d)[4], const uint32_t (&a)[4],
                                       const uint32_t (&b)[2]) {
    asm volatile(
        "mma.sync.aligned.m16n8k32.row.col.s32.s8.s8.s32 "
        "{%0,%1,%2,%3}, {%4,%5,%6,%7}, {%8,%9}, {%0,%1,%2,%3};"
        : "+r"(d[0]), "+r"(d[1]), "+r"(d[2]), "+r"(d[3])
        : "r"(a[0]), "r"(a[1]), "r"(a[2]), "r"(a[3]), "r"(b[0]), "r"(b[1]));
}

#define CP_ASYNC16(dst, src) \
    asm volatile("cp.async.cg.shared.global [%0], [%1], 16;" :: "r"(dst), "l"(src))
#define CP_COMMIT() asm volatile("cp.async.commit_group;" ::: "memory")
#define CP_WAIT0()  asm volatile("cp.async.wait_group 0;" ::: "memory")

__device__ __forceinline__ uint32_t pack_s8x4(int a, int b, int c, int d) {
    return (uint32_t)(a & 0xFF) | ((uint32_t)(b & 0xFF) << 8) |
           ((uint32_t)(c & 0xFF) << 16) | ((uint32_t)(d & 0xFF) << 24);
}

__device__ __forceinline__ void grid_barrier() {
    __syncthreads();
    if (threadIdx.x == 0) {
        __threadfence();
        int gen = *((volatile int*)&g_bar_gen);
        if (atomicAdd(&g_bar_count, 1) == (int)gridDim.x - 1) {
            atomicExch(&g_bar_count, 0);
            __threadfence();
            *((volatile int*)&g_bar_gen) = gen + 1;
        } else {
            while (*((volatile int*)&g_bar_gen) == gen) __nanosleep(64);
        }
        __threadfence();
    }
    __syncthreads();
}

__host__ __device__ __forceinline__ int perm_col(int n) {
    int grp = n >> 5, L = n & 31, Q = L >> 2, r = L & 3;
    int pl = ((Q & 3) << 1) + (r & 1) + (((Q >> 2) << 1) + (r >> 1)) * 8;
    return (grp << 5) + pl;
}

// ---------------------------------------------------------------------------
// Prep kernels
// ---------------------------------------------------------------------------
__global__ void sens_rowmax(const float* __restrict__ base, const float* __restrict__ visual)
{
    int row = blockIdx.x;                    // row = t*512 + b
    int t = row >> 9, b = row & 511;
    const float* pb = base   + ((size_t)b * TSEQ + t) * EBD;
    const float* pv = visual + ((size_t)b * TSEQ + t) * VFD;
    float m = 0.f;
    for (int i = threadIdx.x; i < EBD; i += 128) m = fmaxf(m, fabsf(pb[i]));
    for (int i = threadIdx.x; i < VFD; i += 128) m = fmaxf(m, fabsf(pv[i]));
    for (int o = 16; o; o >>= 1) m = fmaxf(m, __shfl_xor_sync(0xFFFFFFFFu, m, o));
    __shared__ float sm[4];
    if ((threadIdx.x & 31) == 0) sm[threadIdx.x >> 5] = m;
    __syncthreads();
    if (threadIdx.x == 0) {
        m = fmaxf(fmaxf(sm[0], sm[1]), fmaxf(sm[2], sm[3]));
        m = fmaxf(m, 1e-20f);
        g_qc[row] = 127.f / m;
        g_ir[row] = m / 127.f;
    }
}

__global__ void w_colmax(const float* w00, const float* w01, const float* w02, const float* w03, const float* mk0,
                         const float* w10, const float* w11, const float* w12, const float* w13, const float* mk1,
                         const float* w20, const float* w21, const float* w22, const float* w23, const float* mk2)
{
    int idx = blockIdx.x * blockDim.x + threadIdx.x;
    if (idx >= 3328) return;
    const float *w, *mk; int C, j, q;
    if (idx < 2048)      { int c = idx;        q = c & 3; j = c >> 2; C = C0;
                           w = q==0?w00:q==1?w01:q==2?w02:w03; mk = mk0; }
    else if (idx < 3072) { int c = idx - 2048; q = c & 3; j = c >> 2; C = C1;
                           w = q==0?w10:q==1?w11:q==2?w12:w13; mk = mk1; }
    else                 { int c = idx - 3072; q = c & 3; j = c >> 2; C = C2;
                           w = q==0?w20:q==1?w21:q==2?w22:w23; mk = mk2; }
    float m = 0.f;
    for (int k = 0; k < C; k++) {
        float v = w[(size_t)j * C + k];
        if (q < 2) v *= mk[(size_t)j * C + k];
        m = fmaxf(m, fabsf(v));
    }
    m = fmaxf(m, 1e-20f);
    g_cw [idx] = 127.f / m;
    g_wsL[idx] = m / 127.f;
    if (idx < 2048) g_wsP0[perm_col(idx)] = m / 127.f;
}

__global__ void prep_w_all(const float* w00, const float* w01, const float* w02, const float* w03, const float* mk0,
                           const float* w10, const float* w11, const float* w12, const float* w13, const float* mk1,
                           const float* w20, const float* w21, const float* w22, const float* w23, const float* mk2)
{
    const int E0 = C0 * H0, E1 = C1 * H1, E2 = C2 * H2;
    int idx = blockIdx.x * blockDim.x + threadIdx.x;
    if (idx >= E0 + E1 + E2) return;

    const float *wq[4], *mk; int C, H, loff, k, j;
    char* bas; int KC, kc, kr;
    if (idx < E0) {
        C = C0; H = H0; loff = 0;
        wq[0]=w00; wq[1]=w01; wq[2]=w02; wq[3]=w03; mk = mk0;
        k = idx / H; j = idx - k * H;
        if (k < SENSD) { bas = (char*)g_W0x; KC = 6; kc = k >> 7;          kr = k & 127; }
        else           { bas = (char*)g_W0h; KC = 4; kc = (k-SENSD) >> 7;  kr = (k-SENSD) & 127; }
    } else if (idx < E0 + E1) {
        int i = idx - E0; C = C1; H = H1; loff = 2048;
        wq[0]=w10; wq[1]=w11; wq[2]=w12; wq[3]=w13; mk = mk1;
        k = i / H; j = i - k * H;
        bas = (char*)g_W1; KC = 6; kc = k >> 7; kr = k & 127;
    } else {
        int i = idx - E0 - E1; C = C2; H = H2; loff = 3072;
        wq[0]=w20; wq[1]=w21; wq[2]=w22; wq[3]=w23; mk = mk2;
        k = i / H; j = i - k * H;
        bas = (char*)g_W2; KC = 3; kc = k >> 7; kr = k & 127;
    }
    float mval = mk[(size_t)j * C + k];
#pragma unroll
    for (int q = 0; q < 4; q++) {
        float v = wq[q][(size_t)j * C + k];
        if (q < 2) v *= mval;
        float c = g_cw[loff + 4 * j + q];
        float s  = v * c;
        float w1 = rintf(s);
        float w2 = rintf((s - w1) * 254.f);
        int P = perm_col(4 * j + q);
        int nb = P >> 7, nr = P & 127;
        size_t blk = (size_t)(nb * KC + kc) * 32768;
        uint32_t off = SWZ((uint32_t)(nr * 128 + kr));
        bas[blk + off]         = (char)(int)w1;
        bas[blk + 16384 + off] = (char)(int)w2;
    }
}

__global__ void prep_misc(const float* b00, const float* b01, const float* b02, const float* b03,
                          const float* b10, const float* b11, const float* b12, const float* b13,
                          const float* b20, const float* b21, const float* b22, const float* b23)
{
    const int ZH0 = BATCH * H0, ZH1 = BATCH * H1, ZH2 = BATCH * H2;
    int idx = blockIdx.x * blockDim.x + threadIdx.x;
    if (idx < 3328) {
        const float* b; int j, q;
        if (idx < 2048)      { int c = idx;        q = c & 3; j = c >> 2; b = q==0?b00:q==1?b01:q==2?b02:b03; }
        else if (idx < 3072) { int c = idx - 2048; q = c & 3; j = c >> 2; b = q==0?b10:q==1?b11:q==2?b12:b13; }
        else                 { int c = idx - 3072; q = c & 3; j = c >> 2; b = q==0?b20:q==1?b21:q==2?b22:b23; }
        g_bias[idx] = b[j];
        return;
    }
    int z = idx - 3328;
    if (z < ZH0) { g_h0[z] = 0.f; return; }
    z -= ZH0;
    if (z < ZH1) { g_h1[z] = 0.f; return; }
    z -= ZH1;
    if (z < ZH2) { g_h2[z] = 0.f; return; }
}

// ---------------------------------------------------------------------------
// int8 double-digit GEMM tile (+ optional fused CfC epilogue).
// Tile 64(M) x 128(N), 8 warps (2M x 4N), warp tile 32x32, K-chunks of 128,
// double-buffered SMEM, cp.async for pre-packed weight blocks.
// Stage: A1 8K | A2 8K | B1 16K | B2 16K = 48KB, x2 stages.
// ---------------------------------------------------------------------------
#define ST_A1 0
#define ST_A2 8192
#define ST_B1 16384
#define ST_B2 32768
#define ST_BYTES 49152
#define SMEM_BYTES (2 * ST_BYTES)   // 98304

template<bool SENSG, bool CFC>
__device__ void gemm_tile(const float* __restrict__ xa, int Ka,
                          const float* __restrict__ xb, int Kb, int Kt,
                          const char* __restrict__ Wp,
                          const float* __restrict__ bias4,
                          const float* __restrict__ ws4,
                          const float* __restrict__ uadd,
                          float* __restrict__ out,
                          int N, int m0, int nbI, char* smem)
{
    const uint32_t smem_base = smem_u32(smem);

    const int tid  = threadIdx.x;
    const int wid  = tid >> 5;
    const int lane = tid & 31;
    const int wm   = wid >> 2;
    const int wn   = wid & 3;
    const int g    = lane >> 2;
    const int tg   = lane & 3;

    const int n0  = nbI * 128;
    const int nch = (Kt + 127) >> 7;

    int p11[2][4][4], pmd[2][4][4];
#pragma unroll
    for (int a = 0; a < 2; a++)
#pragma unroll
        for (int b = 0; b < 4; b++)
#pragma unroll
            for (int c = 0; c < 4; c++) { p11[a][b][c] = 0; pmd[a][b][c] = 0; }

    // prologue: cp.async B chunk 0 (32KB: digit1 + digit2)
    {
        const char* ws = Wp + (size_t)(nbI * nch) * 32768;
        uint32_t dst = smem_base + ST_B1;
#pragma unroll
        for (int j = 0; j < 8; j++) {
            int i = tid + j * 256;
            CP_ASYNC16(dst + i * 16, ws + i * 16);
        }
        CP_COMMIT();
    }

    for (int ch = 0; ch < nch; ch++) {
        const int bsel = ch & 1;
        char* stage = smem + bsel * ST_BYTES;
        const uint32_t stage_u = smem_base + (uint32_t)bsel * ST_BYTES;
        const int k0 = ch << 7;

        // ---- A: load fp32, quantize to 2 s8 digits, store swizzled ----
#pragma unroll
        for (int it = 0; it < 8; it++) {
            int idx = tid + it * 256;        // 0..2047
            int row = idx >> 5, cg = idx & 31;
            int gm  = m0 + row;
            int kg  = k0 + cg * 4;
            float4 v = make_float4(0.f, 0.f, 0.f, 0.f);
            float qc = 127.f;
            if (SENSG) {
                int t = gm >> 9, bb = gm & 511;
                qc = g_qc[gm];
                if (kg < EBD) v = *(const float4*)(xa + (size_t)(bb * TSEQ + t) * EBD + kg);
                else          v = *(const float4*)(xb + (size_t)(bb * TSEQ + t) * VFD + (kg - EBD));
            } else {
                if (kg < Ka)      v = *(const float4*)(xa + (size_t)gm * Ka + kg);
                else if (kg < Kt) v = *(const float4*)(xb + (size_t)gm * Kb + (kg - Ka));
            }
            float s0 = v.x * qc, s1 = v.y * qc, s2 = v.z * qc, s3 = v.w * qc;
            float h0 = rintf(s0), h1 = rintf(s1), h2 = rintf(s2), h3 = rintf(s3);
            float l0 = rintf((s0 - h0) * 254.f), l1 = rintf((s1 - h1) * 254.f);
            float l2 = rintf((s2 - h2) * 254.f), l3 = rintf((s3 - h3) * 254.f);
            uint32_t off = SWZ((uint32_t)(row * 128 + cg * 4));
            *(uint32_t*)(stage + ST_A1 + off) = pack_s8x4((int)h0, (int)h1, (int)h2, (int)h3);
            *(uint32_t*)(stage + ST_A2 + off) = pack_s8x4((int)l0, (int)l1, (int)l2, (int)l3);
        }

        CP_WAIT0();
        __syncthreads();

        // ---- prefetch next B chunk (overlaps MMAs below) ----
        if (ch + 1 < nch) {
            const char* ws = Wp + (size_t)(nbI * nch + ch + 1) * 32768;
            uint32_t dst = smem_base + (uint32_t)((ch + 1) & 1) * ST_BYTES + ST_B1;
#pragma unroll
            for (int j = 0; j < 8; j++) {
                int i = tid + j * 256;
                CP_ASYNC16(dst + i * 16, ws + i * 16);
            }
            CP_COMMIT();
        }

        // ---- MMAs: 4 k32 steps per 128-chunk ----
        const uint32_t sA1 = stage_u + ST_A1;
        const uint32_t sA2 = stage_u + ST_A2;
        const uint32_t sB1 = stage_u + ST_B1;
        const uint32_t sB2 = stage_u + ST_B2;
#pragma unroll
        for (int ks = 0; ks < 4; ks++) {
            uint32_t a1[2][4], a2[2][4], b1[4][2], b2[4][2];
#pragma unroll
            for (int mt = 0; mt < 2; mt++) {
                int arow = wm * 32 + mt * 16 + (lane & 15);
                uint32_t aoff = SWZ((uint32_t)(arow * 128 + ks * 32 + (lane >> 4) * 16));
                LDSM_X4(a1[mt][0], a1[mt][1], a1[mt][2], a1[mt][3], sA1 + aoff);
                LDSM_X4(a2[mt][0], a2[mt][1], a2[mt][2], a2[mt][3], sA2 + aoff);
            }
#pragma unroll
            for (int nt = 0; nt < 4; nt++) {
                int brow = wn * 32 + nt * 8 + (lane & 7);
                uint32_t boff = SWZ((uint32_t)(brow * 128 + ks * 32 + ((lane >> 3) & 1) * 16));
                LDSM_X2(b1[nt][0], b1[nt][1], sB1 + boff);
                LDSM_X2(b2[nt][0], b2[nt][1], sB2 + boff);
            }
#pragma unroll
            for (int mt = 0; mt < 2; mt++)
#pragma unroll
                for (int nt = 0; nt < 4; nt++) {
                    mma_s8(p11[mt][nt], a1[mt], b1[nt]);
                    mma_s8(pmd[mt][nt], a1[mt], b2[nt]);
                    mma_s8(pmd[mt][nt], a2[mt], b1[nt]);
                }
        }
        __syncthreads();
    }

    // ---- epilogue ----
    const float INV254 = 1.f / 254.f;
    if (CFC) {
        const int Hd = N >> 2;
        const float INV127 = 1.f / 127.f;
#pragma unroll
        for (int mt = 0; mt < 2; mt++) {
#pragma unroll
            for (int rh = 0; rh < 2; rh++) {
                int row = m0 + wm * 32 + mt * 16 + rh * 8 + g;
#pragma unroll
                for (int qi = 0; qi < 2; qi++) {
                    int ntA = 2 * qi, ntB = 2 * qi + 1;
                    float f1  = (float)p11[mt][ntA][rh*2+0] + (float)pmd[mt][ntA][rh*2+0] * INV254;
                    float f2  = (float)p11[mt][ntA][rh*2+1] + (float)pmd[mt][ntA][rh*2+1] * INV254;
                    float tav = (float)p11[mt][ntB][rh*2+0] + (float)pmd[mt][ntB][rh*2+0] * INV254;
                    float tbv = (float)p11[mt][ntB][rh*2+1] + (float)pmd[mt][ntB][rh*2+1] * INV254;
                    int j = (n0 >> 2) + wn * 8 + qi * 4 + tg;
                    float4 ws = *(const float4*)(ws4 + 4 * j);
                    float4 bq = *(const float4*)(bias4 + 4 * j);
                    f1  = f1  * ws.x * INV127 + bq.x;
                    f2  = f2  * ws.y * INV127 + bq.y;
                    tav = tav * ws.z * INV127 + bq.z;
                    tbv = tbv * ws.w * INV127 + bq.w;
                    if (uadd != nullptr) {
                        int pc = n0 + wn * 32 + qi * 16 + tg * 2;
                        float2 u01 = *(const float2*)(uadd + (size_t)row * N + pc);
                        float2 u23 = *(const float2*)(uadd + (size_t)row * N + pc + 8);
                        f1 += u01.x; f2 += u01.y; tav += u23.x; tbv += u23.y;
                    }
                    float s = 1.f / (1.f + expf(-(tav + tbv)));
                    out[(size_t)row * Hd + j] = tanhf(f1) * (1.f - s) + s * tanhf(f2);
                }
            }
        }
    } else {
#pragma unroll
        for (int mt = 0; mt < 2; mt++)
#pragma unroll
            for (int rh = 0; rh < 2; rh++) {
                int row = m0 + wm * 32 + mt * 16 + rh * 8 + g;
                float ir = g_ir[row];
#pragma unroll
                for (int nt = 0; nt < 4; nt++) {
                    int col = n0 + wn * 32 + nt * 8 + tg * 2;
                    float2 wp = *(const float2*)(g_wsP0 + col);
                    float v0 = ((float)p11[mt][nt][rh*2+0] + (float)pmd[mt][nt][rh*2+0] * INV254) * wp.x * ir;
                    float v1 = ((float)p11[mt][nt][rh*2+1] + (float)pmd[mt][nt][rh*2+1] * INV254) * wp.y * ir;
                    *(float2*)(out + (size_t)row * N + col) = make_float2(v0, v1);
                }
            }
    }
}

// ---------------------------------------------------------------------------
// Head kernel: U0 slices 0 and 1 (rows 0..1023), grid (16 nb, 16 mb)
// ---------------------------------------------------------------------------
__global__ __launch_bounds__(256)
void u0_head(const float* __restrict__ base, const float* __restrict__ visual)
{
    extern __shared__ char smem[];
    gemm_tile<true, false>(base, EBD, visual, VFD, SENSD, (const char*)g_W0x,
                           nullptr, nullptr, nullptr,
                           g_U0, N0, blockIdx.y * 64, blockIdx.x, smem);
}

// ---------------------------------------------------------------------------
// Fused per-step kernel: 3 layer phases + grid barriers; idle CTAs weave
// U0 slice (t+2) tiles (128 tiles: 20 + 84 + 24). grid = 148 CTAs.
// ---------------------------------------------------------------------------
__global__ __launch_bounds__(256)
void step_kernel(const float* __restrict__ base, const float* __restrict__ visual,
                 float* __restrict__ dout, int t)
{
    extern __shared__ char smem[];
    const int c = (int)blockIdx.x;
    const int tw = t + 2;
    const bool weave = (tw < TSEQ);

    const float* h0r = g_h0 + (size_t)(t & 1) * BATCH * H0;
    float*       h0w = g_h0 + (size_t)((t + 1) & 1) * BATCH * H0;
    const float* h1r = g_h1 + (size_t)(t & 1) * BATCH * H1;
    float*       h1w = g_h1 + (size_t)((t + 1) & 1) * BATCH * H1;
    const float* h2r = g_h2 + (size_t)(t & 1) * BATCH * H2;
    float*       h2w = g_h2 + (size_t)((t + 1) & 1) * BATCH * H2;

    // ---- phase 0: layer 0 (128 tiles, K=512) + U0 weave 0..19 ----
    if (c < 128) {
        int nb = c & 15, mb = c >> 4;
        gemm_tile<false, true>(h0r, H0, h0r, 0, H0, (const char*)g_W0h,
                               g_bias, g_wsL,
                               g_U0 + (size_t)t * BATCH * N0,
                               h0w, N0, mb * 64, nb, smem);
    } else if (weave) {
        int u = c - 128;
        int nbu = u & 15, mbu = u >> 4;
        gemm_tile<true, false>(base, EBD, visual, VFD, SENSD, (const char*)g_W0x,
                               nullptr, nullptr, nullptr,
                               g_U0, N0, tw * BATCH + mbu * 64, nbu, smem);
    }
    grid_barrier();

    // ---- phase 1: layer 1 (64 tiles, K=768) + U0 weave 20..103 ----
    if (c < 64) {
        int nb = c & 7, mb = c >> 3;
        gemm_tile<false, true>(h0w, H0, h1r, H1, C1, (const char*)g_W1,
                               g_bias + 2048, g_wsL + 2048, nullptr,
                               h1w, N1, mb * 64, nb, smem);
    } else if (weave) {
        int u = c - 64 + 20;
        int nbu = u & 15, mbu = u >> 4;
        gemm_tile<true, false>(base, EBD, visual, VFD, SENSD, (const char*)g_W0x,
                               nullptr, nullptr, nullptr,
                               g_U0, N0, tw * BATCH + mbu * 64, nbu, smem);
    }
    grid_barrier();

    // ---- phase 2: layer 2 (16 tiles, K=320) + U0 weave 104..127 ----
    if (c < 16) {
        int nb = c & 1, mb = c >> 1;
        float* o2 = (t == TSEQ - 1) ? dout : h2w;
        gemm_tile<false, true>(h1w, H1, h2r, H2, C2, (const char*)g_W2,
                               g_bias + 3072, g_wsL + 3072, nullptr,
                               o2, N2, mb * 64, nb, smem);
    } else if (weave && c < 40) {
        int u = c - 16 + 104;
        int nbu = u & 15, mbu = u >> 4;
        gemm_tile<true, false>(base, EBD, visual, VFD, SENSD, (const char*)g_W0x,
                               nullptr, nullptr, nullptr,
                               g_U0, N0, tw * BATCH + mbu * 64, nbu, smem);
    }
}

// ---------------------------------------------------------------------------
// kernel_launch  (launch order: 5 kernels before step t=0 so ncu -s 5 -c 1
// captures the step kernel)
// ---------------------------------------------------------------------------
extern "C" void kernel_launch(void* const* d_in, const int* in_sizes, int n_in,
                              void* d_out, int out_size)
{
    (void)in_sizes; (void)n_in; (void)out_size;
    const float* base   = (const float*)d_in[0];
    const float* visual = (const float*)d_in[1];

    const float* w[3][4];
    const float* bs[3][4];
    const float* mk[3];
    for (int l = 0; l < 3; l++) {
        int o = 2 + l * 9;
        w[l][0] = (const float*)d_in[o + 0];  bs[l][0] = (const float*)d_in[o + 1];
        w[l][1] = (const float*)d_in[o + 2];  bs[l][1] = (const float*)d_in[o + 3];
        w[l][2] = (const float*)d_in[o + 4];  bs[l][2] = (const float*)d_in[o + 5];
        w[l][3] = (const float*)d_in[o + 6];  bs[l][3] = (const float*)d_in[o + 7];
        mk[l]   = (const float*)d_in[o + 8];
    }

    cudaFuncSetAttribute(u0_head,
                         cudaFuncAttributeMaxDynamicSharedMemorySize, SMEM_BYTES);
    cudaFuncSetAttribute(step_kernel,
                         cudaFuncAttributeMaxDynamicSharedMemorySize, SMEM_BYTES);

    // 1) per-row scales for sensory inputs
    sens_rowmax<<<NROWS, 128>>>(base, visual);
    // 2) per-col weight scales
    w_colmax<<<(3328 + 255) / 256, 256>>>(
        w[0][0], w[0][1], w[0][2], w[0][3], mk[0],
        w[1][0], w[1][1], w[1][2], w[1][3], mk[1],
        w[2][0], w[2][1], w[2][2], w[2][3], mk[2]);
    // 3) quantize + pack all weights
    {
        int tot = C0 * H0 + C1 * H1 + C2 * H2;
        prep_w_all<<<(tot + 255) / 256, 256>>>(
            w[0][0], w[0][1], w[0][2], w[0][3], mk[0],
            w[1][0], w[1][1], w[1][2], w[1][3], mk[1],
            w[2][0], w[2][1], w[2][2], w[2][3], mk[2]);
    }
    // 4) biases + zero initial hidden states
    {
        int tot = 3328 + BATCH * (H0 + H1 + H2);
        prep_misc<<<(tot + 255) / 256, 256>>>(
            bs[0][0], bs[0][1], bs[0][2], bs[0][3],
            bs[1][0], bs[1][1], bs[1][2], bs[1][3],
            bs[2][0], bs[2][1], bs[2][2], bs[2][3]);
    }
    // 5) U0 slices 0,1
    u0_head<<<dim3(16, 16), 256, SMEM_BYTES>>>(base, visual);

    // 6+) fused step loop (step t=0 is launch #6 -> profiled by ncu)
    for (int t = 0; t < TSEQ; t++)
        step_kernel<<<148, 256, SMEM_BYTES>>>(base, visual, (float*)d_out, t);
}

// round 11
// speedup vs baseline: 2.9245x; 2.9245x over previous
#include <cuda_runtime.h>
#include <cuda_bf16.h>
#include <cstdint>
#include <math.h>

// ---------------------------------------------------------------------------
// Problem constants
// ---------------------------------------------------------------------------
#define TSEQ  64
#define BATCH 512
#define EBD   256
#define VFD   512
#define SENSD 768
#define H0    512
#define H1    256
#define H2    64
#define C0    1280
#define C1    768
#define C2    320
#define N0    2048         // 4*H0 physical (gate-interleaved, permuted)
#define N1    1024
#define N2    256
#define NROWS (TSEQ * BATCH)

// ---------------------------------------------------------------------------
// Device-global scratch.
// Weights: per (nb, kc) block = 32 KB: [hi 16KB: 128 n-rows x 64 k bf16,
//   128B rows, SW128][lo 16KB same].
// Hidden states: packed A-tiles, per (mb, kc) block = 16 KB:
//   [hi 8KB: 64 rows x 64 k bf16, 128B rows, SW128][lo 8KB same].
// ---------------------------------------------------------------------------
__device__ float g_W0x[SENSD * N0];   // 16 nb x 12 kc
__device__ float g_W0h[H0 * N0];      // 16 nb x  8 kc
__device__ float g_W1 [C1 * N1];      //  8 nb x 12 kc
__device__ float g_W2 [C2 * N2];      //  2 nb x  5 kc
__device__ float g_b0 [N0];
__device__ float g_b1 [N1];
__device__ float g_b2 [N2];
__device__ float g_U0 [(size_t)NROWS * N0];
__device__ float g_h0 [2 * BATCH * H0];   // packed: 2 x (8 mb x 8 kc x 16KB)
__device__ float g_h1 [2 * BATCH * H1];   // packed: 2 x (8 mb x 4 kc x 16KB)
__device__ float g_h2 [2 * BATCH * H2];   // packed: 2 x (8 mb x 1 kc x 16KB)

__device__ int g_bar_count;
__device__ int g_bar_gen;

// ---------------------------------------------------------------------------
// Helpers (portable PTX only: mma.sync / ldmatrix / cp.async)
// ---------------------------------------------------------------------------
__device__ __forceinline__ uint32_t smem_u32(const void* p) {
    uint32_t a;
    asm("{ .reg .u64 t; cvta.to.shared.u64 t, %1; cvt.u32.u64 %0, t; }" : "=r"(a) : "l"(p));
    return a;
}
#define SWZ(o) ((o) ^ (((o) >> 3) & 0x70))

#define LDSM_X4(r0, r1, r2, r3, a) \
    asm volatile("ldmatrix.sync.aligned.m8n8.x4.shared.b16 {%0,%1,%2,%3}, [%4];" \
                 : "=r"(r0), "=r"(r1), "=r"(r2), "=r"(r3) : "r"(a))

__device__ __forceinline__ void mma16816(float (&d)[4], const uint32_t (&a)[4],
                                         const uint32_t (&b)[2]) {
    asm volatile(
        "mma.sync.aligned.m16n8k16.row.col.f32.bf16.bf16.f32 "
        "{%0,%1,%2,%3}, {%4,%5,%6,%7}, {%8,%9}, {%0,%1,%2,%3};"
        : "+f"(d[0]), "+f"(d[1]), "+f"(d[2]), "+f"(d[3])
        : "r"(a[0]), "r"(a[1]), "r"(a[2]), "r"(a[3]), "r"(b[0]), "r"(b[1]));
}

#define CP_ASYNC16(dst, src) \
    asm volatile("cp.async.cg.shared.global [%0], [%1], 16;" :: "r"(dst), "l"(src))
#define CP_COMMIT() asm volatile("cp.async.commit_group;" ::: "memory")
#define CP_WAIT0()  asm volatile("cp.async.wait_group 0;" ::: "memory")

__device__ __forceinline__ uint32_t pack_bf2(__nv_bfloat16 a, __nv_bfloat16 b) {
    uint16_t ua = *(uint16_t*)&a, ub = *(uint16_t*)&b;
    return (uint32_t)ua | ((uint32_t)ub << 16);
}

__device__ __forceinline__ void grid_barrier() {
    __syncthreads();
    if (threadIdx.x == 0) {
        __threadfence();
        int gen = *((volatile int*)&g_bar_gen);
        if (atomicAdd(&g_bar_count, 1) == (int)gridDim.x - 1) {
            atomicExch(&g_bar_count, 0);
            __threadfence();
            *((volatile int*)&g_bar_gen) = gen + 1;
        } else {
            while (*((volatile int*)&g_bar_gen) == gen) __nanosleep(64);
        }
        __threadfence();
    }
    __syncthreads();
}

__host__ __device__ __forceinline__ int perm_col(int n) {
    int grp = n >> 5, L = n & 31, Q = L >> 2, r = L & 3;
    int pl = ((Q & 3) << 1) + (r & 1) + (((Q >> 2) << 1) + (r >> 1)) * 8;
    return (grp << 5) + pl;
}

// ---------------------------------------------------------------------------
// Weight prep (same as proven R8): masked, hi/lo split, transposed [n][k],
// gate-interleaved + permuted, scattered into swizzled 32KB blocks.
// ---------------------------------------------------------------------------
__global__ void prep_weights(const float* __restrict__ ff1, const float* __restrict__ ff2,
                             const float* __restrict__ ta,  const float* __restrict__ tb,
                             const float* __restrict__ mask,
                             float* __restrict__ Wx, int Kx, int KCx,
                             float* __restrict__ Wh, int KCh,
                             int C, int H)
{
    int idx = blockIdx.x * blockDim.x + threadIdx.x;
    if (idx >= C * H) return;
    int k = idx / H;
    int j = idx - k * H;
    float mk = mask[j * C + k];
    float v[4];
    v[0] = ff1[j * C + k] * mk;
    v[1] = ff2[j * C + k] * mk;
    v[2] = ta [j * C + k];
    v[3] = tb [j * C + k];

    char* base; int kc, KC;
    if (k < Kx) { base = (char*)Wx; kc = k >> 6;        KC = KCx; }
    else        { base = (char*)Wh; kc = (k - Kx) >> 6; KC = KCh; }
    int kr = (k < Kx ? k : k - Kx) & 63;

#pragma unroll
    for (int q = 0; q < 4; q++) {
        int P  = perm_col(4 * j + q);
        int nb = P >> 7, nr = P & 127;
        size_t blk = (size_t)(nb * KC + kc) * 32768;
        uint32_t off = SWZ((uint32_t)(nr * 128 + kr * 2));
        float x = v[q];
        __nv_bfloat16 h = __float2bfloat16(x);
        __nv_bfloat16 l = __float2bfloat16(x - __bfloat162float(h));
        *(__nv_bfloat16*)(base + blk + off)         = h;
        *(__nv_bfloat16*)(base + blk + 16384 + off) = l;
    }
}

__global__ void prep_bias(const float* __restrict__ b1, const float* __restrict__ b2,
                          const float* __restrict__ b3, const float* __restrict__ b4,
                          float* __restrict__ bo, int H)
{
    int j = blockIdx.x * blockDim.x + threadIdx.x;
    if (j >= H) return;
    bo[4 * j + 0] = b1[j];
    bo[4 * j + 1] = b2[j];
    bo[4 * j + 2] = b3[j];
    bo[4 * j + 3] = b4[j];
}

__global__ void zero_kernel(float* __restrict__ p, int n)
{
    int i = blockIdx.x * blockDim.x + threadIdx.x;
    if (i < n) p[i] = 0.f;
}

// ---------------------------------------------------------------------------
// Split-bf16 HMMA GEMM tile (+ optional fused CfC epilogue).
// Tile 64(M) x 128(N), 8 warps (2M x 4N), warp tile 32x32, K-chunks of 64,
// double-buffered SMEM.
//   SENSG=true : A = sensory fp32, converted in-loop (U0 path)
//   SENSG=false: A = packed split-bf16 tiles (hidden states), cp.async'd
// Stage: AH 8K | AL 8K | BH 16K | BL 16K = 48KB, x2 stages.
// ---------------------------------------------------------------------------
#define ST_AH 0
#define ST_AL 8192
#define ST_BH 16384
#define ST_BL 32768
#define ST_BYTES 49152
#define SMEM_BYTES (2 * ST_BYTES)   // 98304

__device__ __forceinline__ void load_a_sens(const float* __restrict__ xa,
                                            const float* __restrict__ xb,
                                            int m0, int k0, int tid, float* ar)
{
#pragma unroll
    for (int it = 0; it < 4; it++) {
        int idx = tid + it * 256;
        int row = idx >> 4, cg = idx & 15;
        int gm  = m0 + row;
        int kg  = k0 + cg * 4;
        int t = gm >> 9, bb = gm & 511;
        const float* src;
        if (kg < EBD) src = xa + (size_t)(bb * TSEQ + t) * EBD + kg;
        else          src = xb + (size_t)(bb * TSEQ + t) * VFD + (kg - EBD);
        float4 v = *(const float4*)src;
        ar[it * 4 + 0] = v.x; ar[it * 4 + 1] = v.y;
        ar[it * 4 + 2] = v.z; ar[it * 4 + 3] = v.w;
    }
}

template<bool SENSG, bool CFC>
__device__ void gemm_tile(const float* __restrict__ xa,   // SENSG: base
                          const float* __restrict__ xb,   // SENSG: visual
                          const char* __restrict__ apA, int KCa,  // packed A part 1
                          const char* __restrict__ apB,   // packed A part 2 (or null)
                          const char* __restrict__ Wp,
                          const float* __restrict__ bias,
                          const float* __restrict__ uadd,
                          char* __restrict__ outPack, int KCout,  // CFC packed out
                          float* __restrict__ outF,               // fp32 out (U0/dout)
                          int N, int nch, int m0, int nbI, char* smem)
{
    const uint32_t smem_base = smem_u32(smem);

    const int tid  = threadIdx.x;
    const int wid  = tid >> 5;
    const int lane = tid & 31;
    const int wm   = wid >> 2;
    const int wn   = wid & 3;
    const int g    = lane >> 2;
    const int tg   = lane & 3;

    const int n0 = nbI * 128;
    const int mb = m0 >> 6;

    float acc[2][4][4];
#pragma unroll
    for (int a = 0; a < 2; a++)
#pragma unroll
        for (int b = 0; b < 4; b++)
#pragma unroll
            for (int c = 0; c < 4; c++) acc[a][b][c] = 0.f;

    float ar[16];
    if (SENSG) load_a_sens(xa, xb, m0, 0, tid, ar);

    // ---- prologue: async-copy chunk 0 (A packed if !SENSG, B always) ----
    {
        uint32_t dst = smem_base;
        if (!SENSG) {
            const char* ab = (0 < KCa)
                ? apA + (size_t)(mb * KCa) * 16384
                : apB + (size_t)(mb * 1) * 16384;   // unreachable when KCa>0
#pragma unroll
            for (int j = 0; j < 4; j++) {
                int i = tid + j * 256;
                CP_ASYNC16(dst + ST_AH + i * 16, ab + i * 16);
            }
        }
        const char* ws = Wp + (size_t)(nbI * nch) * 32768;
#pragma unroll
        for (int j = 0; j < 8; j++) {
            int i = tid + j * 256;
            CP_ASYNC16(dst + ST_BH + i * 16, ws + i * 16);
        }
        CP_COMMIT();
    }

    for (int ch = 0; ch < nch; ch++) {
        const int bsel = ch & 1;
        char* stage = smem + bsel * ST_BYTES;
        const uint32_t stage_u = smem_base + (uint32_t)bsel * ST_BYTES;

        if (SENSG) {
            // convert-store A for this chunk from preloaded registers
#pragma unroll
            for (int it = 0; it < 4; it++) {
                int idx = tid + it * 256;
                int row = idx >> 4, cg = idx & 15;
                float x0 = ar[it * 4 + 0], x1 = ar[it * 4 + 1];
                float x2 = ar[it * 4 + 2], x3 = ar[it * 4 + 3];
                __nv_bfloat16 h0 = __float2bfloat16(x0);
                __nv_bfloat16 h1 = __float2bfloat16(x1);
                __nv_bfloat16 h2 = __float2bfloat16(x2);
                __nv_bfloat16 h3 = __float2bfloat16(x3);
                __nv_bfloat16 l0 = __float2bfloat16(x0 - __bfloat162float(h0));
                __nv_bfloat16 l1 = __float2bfloat16(x1 - __bfloat162float(h1));
                __nv_bfloat16 l2 = __float2bfloat16(x2 - __bfloat162float(h2));
                __nv_bfloat16 l3 = __float2bfloat16(x3 - __bfloat162float(h3));
                uint32_t off = SWZ((uint32_t)(row * 128 + cg * 8));
                *(uint2*)(stage + ST_AH + off) = make_uint2(pack_bf2(h0, h1), pack_bf2(h2, h3));
                *(uint2*)(stage + ST_AL + off) = make_uint2(pack_bf2(l0, l1), pack_bf2(l2, l3));
            }
        }

        CP_WAIT0();
        __syncthreads();

        // ---- prefetch chunk ch+1 (overlaps MMAs below) ----
        if (ch + 1 < nch) {
            uint32_t dst = smem_base + (uint32_t)((ch + 1) & 1) * ST_BYTES;
            if (!SENSG) {
                int kc = ch + 1;
                const char* ab = (kc < KCa)
                    ? apA + (size_t)(mb * KCa + kc) * 16384
                    : apB + (size_t)(mb * (nch - KCa) + (kc - KCa)) * 16384;
#pragma unroll
                for (int j = 0; j < 4; j++) {
                    int i = tid + j * 256;
                    CP_ASYNC16(dst + ST_AH + i * 16, ab + i * 16);
                }
            }
            const char* ws = Wp + (size_t)(nbI * nch + ch + 1) * 32768;
#pragma unroll
            for (int j = 0; j < 8; j++) {
                int i = tid + j * 256;
                CP_ASYNC16(dst + ST_BH + i * 16, ws + i * 16);
            }
            CP_COMMIT();
            if (SENSG) load_a_sens(xa, xb, m0, (ch + 1) << 6, tid, ar);
        }

        // ---- MMAs: 4 k16 steps per 64-chunk ----
        const uint32_t sAh = stage_u + ST_AH;
        const uint32_t sAl = stage_u + ST_AL;
        const uint32_t sBh = stage_u + ST_BH;
        const uint32_t sBl = stage_u + ST_BL;
#pragma unroll
        for (int ks = 0; ks < 4; ks++) {
            uint32_t ah[2][4], al[2][4], bh[4][2], bl[4][2];
#pragma unroll
            for (int mt = 0; mt < 2; mt++) {
                int arow = wm * 32 + mt * 16 + (lane & 15);
                uint32_t aoff = SWZ((uint32_t)(arow * 128 + (ks * 16 + (lane >> 4) * 8) * 2));
                LDSM_X4(ah[mt][0], ah[mt][1], ah[mt][2], ah[mt][3], sAh + aoff);
                LDSM_X4(al[mt][0], al[mt][1], al[mt][2], al[mt][3], sAl + aoff);
            }
#pragma unroll
            for (int nt = 0; nt < 4; nt += 2) {
                int brow = wn * 32 + nt * 8 + ((lane >> 4) & 1) * 8 + (lane & 7);
                uint32_t boff = SWZ((uint32_t)(brow * 128 + (ks * 16 + ((lane >> 3) & 1) * 8) * 2));
                LDSM_X4(bh[nt][0], bh[nt][1], bh[nt + 1][0], bh[nt + 1][1], sBh + boff);
                LDSM_X4(bl[nt][0], bl[nt][1], bl[nt + 1][0], bl[nt + 1][1], sBl + boff);
            }
#pragma unroll
            for (int mt = 0; mt < 2; mt++)
#pragma unroll
                for (int nt = 0; nt < 4; nt++) {
                    mma16816(acc[mt][nt], ah[mt], bh[nt]);
                    mma16816(acc[mt][nt], ah[mt], bl[nt]);
                    mma16816(acc[mt][nt], al[mt], bh[nt]);
                }
        }
        __syncthreads();
    }

    // ---- epilogue ----
    if (CFC) {
        const int Hd = N >> 2;
        const int jbase = n0 >> 2;
        char* ob = outPack + (size_t)(mb * KCout + (jbase >> 6)) * 16384;
#pragma unroll
        for (int mt = 0; mt < 2; mt++) {
#pragma unroll
            for (int rh = 0; rh < 2; rh++) {
                int row = m0 + wm * 32 + mt * 16 + rh * 8 + g;
#pragma unroll
                for (int qi = 0; qi < 2; qi++) {
                    float f1  = acc[mt][2 * qi + 0][rh * 2 + 0];
                    float f2  = acc[mt][2 * qi + 0][rh * 2 + 1];
                    float tav = acc[mt][2 * qi + 1][rh * 2 + 0];
                    float tbv = acc[mt][2 * qi + 1][rh * 2 + 1];
                    int j = jbase + wn * 8 + qi * 4 + tg;
                    float4 bq = *(const float4*)(bias + 4 * j);
                    f1 += bq.x; f2 += bq.y; tav += bq.z; tbv += bq.w;
                    if (uadd != nullptr) {
                        int pc = n0 + wn * 32 + qi * 16 + tg * 2;
                        float2 u01 = *(const float2*)(uadd + (size_t)row * N + pc);
                        float2 u23 = *(const float2*)(uadd + (size_t)row * N + pc + 8);
                        f1 += u01.x; f2 += u01.y; tav += u23.x; tbv += u23.y;
                    }
                    float s = 1.f / (1.f + expf(-(tav + tbv)));
                    float h = tanhf(f1) * (1.f - s) + s * tanhf(f2);
                    // packed split-bf16 write (next step's A tile)
                    __nv_bfloat16 hh = __float2bfloat16(h);
                    __nv_bfloat16 hl = __float2bfloat16(h - __bfloat162float(hh));
                    uint32_t off = SWZ((uint32_t)((row & 63) * 128 + (j & 63) * 2));
                    *(__nv_bfloat16*)(ob + off)        = hh;
                    *(__nv_bfloat16*)(ob + 8192 + off) = hl;
                    if (outF != nullptr)
                        outF[(size_t)row * Hd + j] = h;
                }
            }
        }
    } else {
#pragma unroll
        for (int mt = 0; mt < 2; mt++)
#pragma unroll
            for (int rh = 0; rh < 2; rh++) {
                int row = m0 + wm * 32 + mt * 16 + rh * 8 + g;
#pragma unroll
                for (int nt = 0; nt < 4; nt++) {
                    int col = n0 + wn * 32 + nt * 8 + tg * 2;
                    float2 v = make_float2(acc[mt][nt][rh * 2 + 0], acc[mt][nt][rh * 2 + 1]);
                    *(float2*)(outF + (size_t)row * N + col) = v;
                }
            }
    }
}

// ---------------------------------------------------------------------------
// Head kernel: U0 slices 0 and 1 (rows 0..1023), grid (16 nb, 16 mb)
// ---------------------------------------------------------------------------
__global__ __launch_bounds__(256, 2)
void u0_head(const float* __restrict__ base, const float* __restrict__ visual)
{
    extern __shared__ char smem[];
    gemm_tile<true, false>(base, visual, nullptr, 0, nullptr,
                           (const char*)g_W0x, nullptr, nullptr,
                           nullptr, 0, g_U0,
                           N0, 12, blockIdx.y * 64, blockIdx.x, smem);
}

// ---------------------------------------------------------------------------
// Fused per-step kernel: 3 layer phases + grid barriers; idle CTAs weave
// U0 slice (t+2) tiles (128 tiles: 20 + 84 + 24). grid = 148 CTAs.
// ---------------------------------------------------------------------------
__global__ __launch_bounds__(256, 2)
void step_kernel(const float* __restrict__ base, const float* __restrict__ visual,
                 float* __restrict__ dout, int t)
{
    extern __shared__ char smem[];
    const int c = (int)blockIdx.x;
    const int tw = t + 2;
    const bool weave = (tw < TSEQ);

    const char* h0r = (const char*)g_h0 + (size_t)(t & 1) * (BATCH * H0 * 4);
    char*       h0w = (char*)g_h0 + (size_t)((t + 1) & 1) * (BATCH * H0 * 4);
    const char* h1r = (const char*)g_h1 + (size_t)(t & 1) * (BATCH * H1 * 4);
    char*       h1w = (char*)g_h1 + (size_t)((t + 1) & 1) * (BATCH * H1 * 4);
    const char* h2r = (const char*)g_h2 + (size_t)(t & 1) * (BATCH * H2 * 4);
    char*       h2w = (char*)g_h2 + (size_t)((t + 1) & 1) * (BATCH * H2 * 4);

    // ---- phase 0: layer 0 (128 tiles, K=512) + U0 weave 0..19 ----
    if (c < 128) {
        int nb = c & 15, mb = c >> 4;
        gemm_tile<false, true>(nullptr, nullptr, h0r, 8, nullptr,
                               (const char*)g_W0h, g_b0,
                               g_U0 + (size_t)t * BATCH * N0,
                               h0w, 8, nullptr,
                               N0, 8, mb * 64, nb, smem);
    } else if (weave) {
        int u = c - 128;
        int nbu = u & 15, mbu = u >> 4;
        gemm_tile<true, false>(base, visual, nullptr, 0, nullptr,
                               (const char*)g_W0x, nullptr, nullptr,
                               nullptr, 0, g_U0,
                               N0, 12, tw * BATCH + mbu * 64, nbu, smem);
    }
    grid_barrier();

    // ---- phase 1: layer 1 (64 tiles, K=768) + U0 weave 20..103 ----
    if (c < 64) {
        int nb = c & 7, mb = c >> 3;
        gemm_tile<false, true>(nullptr, nullptr, h0w, 8, h1r,
                               (const char*)g_W1, g_b1, nullptr,
                               h1w, 4, nullptr,
                               N1, 12, mb * 64, nb, smem);
    } else if (weave) {
        int u = c - 64 + 20;
        int nbu = u & 15, mbu = u >> 4;
        gemm_tile<true, false>(base, visual, nullptr, 0, nullptr,
                               (const char*)g_W0x, nullptr, nullptr,
                               nullptr, 0, g_U0,
                               N0, 12, tw * BATCH + mbu * 64, nbu, smem);
    }
    grid_barrier();

    // ---- phase 2: layer 2 (16 tiles, K=320) + U0 weave 104..127 ----
    if (c < 16) {
        int nb = c & 1, mb = c >> 1;
        float* o2 = (t == TSEQ - 1) ? dout : nullptr;
        gemm_tile<false, true>(nullptr, nullptr, h1w, 4, h2r,
                               (const char*)g_W2, g_b2, nullptr,
                               h2w, 1, o2,
                               N2, 5, mb * 64, nb, smem);
    } else if (weave && c < 40) {
        int u = c - 16 + 104;
        int nbu = u & 15, mbu = u >> 4;
        gemm_tile<true, false>(base, visual, nullptr, 0, nullptr,
                               (const char*)g_W0x, nullptr, nullptr,
                               nullptr, 0, g_U0,
                               N0, 12, tw * BATCH + mbu * 64, nbu, smem);
    }
}

// ---------------------------------------------------------------------------
// kernel_launch
// ---------------------------------------------------------------------------
extern "C" void kernel_launch(void* const* d_in, const int* in_sizes, int n_in,
                              void* d_out, int out_size)
{
    (void)in_sizes; (void)n_in; (void)out_size;
    const float* base   = (const float*)d_in[0];
    const float* visual = (const float*)d_in[1];

    const float* w[3][4];
    const float* bs[3][4];
    const float* mk[3];
    for (int l = 0; l < 3; l++) {
        int o = 2 + l * 9;
        w[l][0] = (const float*)d_in[o + 0];  bs[l][0] = (const float*)d_in[o + 1];
        w[l][1] = (const float*)d_in[o + 2];  bs[l][1] = (const float*)d_in[o + 3];
        w[l][2] = (const float*)d_in[o + 4];  bs[l][2] = (const float*)d_in[o + 5];
        w[l][3] = (const float*)d_in[o + 6];  bs[l][3] = (const float*)d_in[o + 7];
        mk[l]   = (const float*)d_in[o + 8];
    }

    void* p;
    cudaGetSymbolAddress(&p, g_W0x); float* pW0x = (float*)p;
    cudaGetSymbolAddress(&p, g_W0h); float* pW0h = (float*)p;
    cudaGetSymbolAddress(&p, g_W1);  float* pW1  = (float*)p;
    cudaGetSymbolAddress(&p, g_W2);  float* pW2  = (float*)p;
    cudaGetSymbolAddress(&p, g_b0);  float* pb0  = (float*)p;
    cudaGetSymbolAddress(&p, g_b1);  float* pb1  = (float*)p;
    cudaGetSymbolAddress(&p, g_b2);  float* pb2  = (float*)p;
    cudaGetSymbolAddress(&p, g_h0);  float* ph0  = (float*)p;
    cudaGetSymbolAddress(&p, g_h1);  float* ph1  = (float*)p;
    cudaGetSymbolAddress(&p, g_h2);  float* ph2  = (float*)p;

    cudaFuncSetAttribute(u0_head,
                         cudaFuncAttributeMaxDynamicSharedMemorySize, SMEM_BYTES);
    cudaFuncSetAttribute(step_kernel,
                         cudaFuncAttributeMaxDynamicSharedMemorySize, SMEM_BYTES);

    // --- prep: pack weights into swizzled bf16 hi/lo blocks, interleave biases ---
    prep_weights<<<(C0 * H0 + 255) / 256, 256>>>(w[0][0], w[0][1], w[0][2], w[0][3], mk[0],
                                                 pW0x, SENSD, 12, pW0h, 8, C0, H0);
    prep_weights<<<(C1 * H1 + 255) / 256, 256>>>(w[1][0], w[1][1], w[1][2], w[1][3], mk[1],
                                                 pW1, C1, 12, pW1, 1, C1, H1);
    prep_weights<<<(C2 * H2 + 255) / 256, 256>>>(w[2][0], w[2][1], w[2][2], w[2][3], mk[2],
                                                 pW2, C2, 5, pW2, 1, C2, H2);
    prep_bias<<<(H0 + 255) / 256, 256>>>(bs[0][0], bs[0][1], bs[0][2], bs[0][3], pb0, H0);
    prep_bias<<<(H1 + 255) / 256, 256>>>(bs[1][0], bs[1][1], bs[1][2], bs[1][3], pb1, H1);
    prep_bias<<<(H2 + 255) / 256, 256>>>(bs[2][0], bs[2][1], bs[2][2], bs[2][3], pb2, H2);

    // --- zero initial hidden states (buffer 0; packed bf16 zeros == 0.0) ---
    zero_kernel<<<(BATCH * H0 + 255) / 256, 256>>>(ph0, BATCH * H0);
    zero_kernel<<<(BATCH * H1 + 255) / 256, 256>>>(ph1, BATCH * H1);
    zero_kernel<<<(BATCH * H2 + 255) / 256, 256>>>(ph2, BATCH * H2);

    // --- U0 slices 0,1 (slice t+2 woven into step t) ---
    u0_head<<<dim3(16, 16), 256, SMEM_BYTES>>>(base, visual);

    // --- fused step loop ---
    for (int t = 0; t < TSEQ; t++)
        step_kernel<<<148, 256, SMEM_BYTES>>>(base, visual, (float*)d_out, t);
}

// round 12
// speedup vs baseline: 3.1508x; 1.0774x over previous
#include <cuda_runtime.h>
#include <cuda_bf16.h>
#include <cstdint>
#include <math.h>

// ---------------------------------------------------------------------------
// Problem constants
// ---------------------------------------------------------------------------
#define TSEQ  64
#define BATCH 512
#define EBD   256
#define VFD   512
#define SENSD 768
#define H0    512
#define H1    256
#define H2    64
#define C0    1280
#define C1    768
#define C2    320
#define N0    2048         // 4*H0 physical (gate-interleaved, permuted)
#define N1    1024
#define N2    256
#define NROWS (TSEQ * BATCH)

#define E0 (C0 * H0)
#define E1 (C1 * H1)
#define E2 (C2 * H2)
#define EW (E0 + E1 + E2)
#define NBIAS 3328
#define NZ (BATCH * (H0 + H1 + H2))

// ---------------------------------------------------------------------------
// Device-global scratch.
// Weights: per (nb, kc) block = 32 KB: [hi 16KB: 128 n-rows x 64 k bf16,
//   128B rows, SW128][lo 16KB same].
// Hidden states: packed A-tiles, per (mb, kc) block = 16 KB:
//   [hi 8KB: 64 rows x 64 k bf16, SW128][lo 8KB same].
// ---------------------------------------------------------------------------
__device__ float g_W0x[SENSD * N0];   // 16 nb x 12 kc
__device__ float g_W0h[H0 * N0];      // 16 nb x  8 kc
__device__ float g_W1 [C1 * N1];      //  8 nb x 12 kc
__device__ float g_W2 [C2 * N2];      //  2 nb x  5 kc
__device__ float g_b0 [N0];
__device__ float g_b1 [N1];
__device__ float g_b2 [N2];
__device__ float g_U0 [(size_t)NROWS * N0];
__device__ float g_h0 [2 * BATCH * H0];   // packed 2 x (8 mb x 8 kc x 16KB)
__device__ float g_h1 [2 * BATCH * H1];   // packed 2 x (8 mb x 4 kc x 16KB)
__device__ float g_h2 [2 * BATCH * H2];   // packed 2 x (8 mb x 1 kc x 16KB)

__device__ int g_bar_count;
__device__ int g_bar_gen;

// ---------------------------------------------------------------------------
// Helpers (portable PTX only: mma.sync / ldmatrix / cp.async)
// ---------------------------------------------------------------------------
__device__ __forceinline__ uint32_t smem_u32(const void* p) {
    uint32_t a;
    asm("{ .reg .u64 t; cvta.to.shared.u64 t, %1; cvt.u32.u64 %0, t; }" : "=r"(a) : "l"(p));
    return a;
}
#define SWZ(o) ((o) ^ (((o) >> 3) & 0x70))

#define LDSM_X4(r0, r1, r2, r3, a) \
    asm volatile("ldmatrix.sync.aligned.m8n8.x4.shared.b16 {%0,%1,%2,%3}, [%4];" \
                 : "=r"(r0), "=r"(r1), "=r"(r2), "=r"(r3) : "r"(a))

__device__ __forceinline__ void mma16816(float (&d)[4], const uint32_t (&a)[4],
                                         const uint32_t (&b)[2]) {
    asm volatile(
        "mma.sync.aligned.m16n8k16.row.col.f32.bf16.bf16.f32 "
        "{%0,%1,%2,%3}, {%4,%5,%6,%7}, {%8,%9}, {%0,%1,%2,%3};"
        : "+f"(d[0]), "+f"(d[1]), "+f"(d[2]), "+f"(d[3])
        : "r"(a[0]), "r"(a[1]), "r"(a[2]), "r"(a[3]), "r"(b[0]), "r"(b[1]));
}

#define CP_ASYNC16(dst, src) \
    asm volatile("cp.async.cg.shared.global [%0], [%1], 16;" :: "r"(dst), "l"(src))
#define CP_COMMIT() asm volatile("cp.async.commit_group;" ::: "memory")
#define CP_WAIT0()  asm volatile("cp.async.wait_group 0;" ::: "memory")

__device__ __forceinline__ uint32_t pack_bf2(__nv_bfloat16 a, __nv_bfloat16 b) {
    uint16_t ua = *(uint16_t*)&a, ub = *(uint16_t*)&b;
    return (uint32_t)ua | ((uint32_t)ub << 16);
}

__device__ __forceinline__ void grid_barrier() {
    __syncthreads();
    if (threadIdx.x == 0) {
        __threadfence();
        int gen = *((volatile int*)&g_bar_gen);
        if (atomicAdd(&g_bar_count, 1) == (int)gridDim.x - 1) {
            atomicExch(&g_bar_count, 0);
            __threadfence();
            *((volatile int*)&g_bar_gen) = gen + 1;
        } else {
            while (*((volatile int*)&g_bar_gen) == gen) __nanosleep(64);
        }
        __threadfence();
    }
    __syncthreads();
}

__host__ __device__ __forceinline__ int perm_col(int n) {
    int grp = n >> 5, L = n & 31, Q = L >> 2, r = L & 3;
    int pl = ((Q & 3) << 1) + (r & 1) + (((Q >> 2) << 1) + (r >> 1)) * 8;
    return (grp << 5) + pl;
}

// ---------------------------------------------------------------------------
// Merged prep kernel: all weights (masked, hi/lo split, transposed,
// gate-interleaved+permuted, swizzled blocks) + biases + zero hidden states.
// ---------------------------------------------------------------------------
struct Params {
    const float* w[3][4];
    const float* b[3][4];
    const float* mk[3];
};

__global__ void prep_all(Params pr)
{
    int idx = blockIdx.x * blockDim.x + threadIdx.x;
    if (idx < EW) {
        int l, i, C, H;
        if (idx < E0)            { l = 0; i = idx;           C = C0; H = H0; }
        else if (idx < E0 + E1)  { l = 1; i = idx - E0;      C = C1; H = H1; }
        else                     { l = 2; i = idx - E0 - E1; C = C2; H = H2; }
        int k = i / H, j = i - k * H;
        float mkv = pr.mk[l][(size_t)j * C + k];
        float v[4];
#pragma unroll
        for (int q = 0; q < 4; q++) v[q] = pr.w[l][q][(size_t)j * C + k];
        v[0] *= mkv; v[1] *= mkv;

        char* bas; int KC, kk;
        if (l == 0) {
            if (k < SENSD) { bas = (char*)g_W0x; KC = 12; kk = k; }
            else           { bas = (char*)g_W0h; KC = 8;  kk = k - SENSD; }
        } else if (l == 1) { bas = (char*)g_W1; KC = 12; kk = k; }
        else               { bas = (char*)g_W2; KC = 5;  kk = k; }
        int kc = kk >> 6, kr = kk & 63;
#pragma unroll
        for (int q = 0; q < 4; q++) {
            int P  = perm_col(4 * j + q);
            int nb = P >> 7, nr = P & 127;
            size_t blk = (size_t)(nb * KC + kc) * 32768;
            uint32_t off = SWZ((uint32_t)(nr * 128 + kr * 2));
            float x = v[q];
            __nv_bfloat16 h = __float2bfloat16(x);
            __nv_bfloat16 lo = __float2bfloat16(x - __bfloat162float(h));
            *(__nv_bfloat16*)(bas + blk + off)         = h;
            *(__nv_bfloat16*)(bas + blk + 16384 + off) = lo;
        }
        return;
    }
    if (idx < EW + NBIAS) {
        int c = idx - EW;
        float* bo; const float* b; int j, q;
        if (c < 2048)      { q = c & 3; j = c >> 2; bo = g_b0; b = pr.b[0][q]; bo += c; }
        else if (c < 3072) { int cc = c - 2048; q = cc & 3; j = cc >> 2; bo = g_b1 + cc; b = pr.b[1][q]; }
        else               { int cc = c - 3072; q = cc & 3; j = cc >> 2; bo = g_b2 + cc; b = pr.b[2][q]; }
        *bo = b[j];
        return;
    }
    int z = idx - EW - NBIAS;
    if (z < NZ) {
        if (z < BATCH * H0)                     g_h0[z] = 0.f;
        else if (z < BATCH * (H0 + H1))         g_h1[z - BATCH * H0] = 0.f;
        else                                    g_h2[z - BATCH * (H0 + H1)] = 0.f;
    }
}

// ---------------------------------------------------------------------------
// Split-bf16 HMMA GEMM tile (+ optional fused CfC epilogue).
// Tile 64(M) x 128(N), 8 warps (2M x 4N), K-chunks of 64, double-buffered.
//   SENSG=true : A = sensory fp32, converted in-loop; supports kc sub-range
//   SENSG=false: A = packed split-bf16 tiles (hidden states), cp.async'd
// Stage: AH 8K | AL 8K | BH 16K | BL 16K = 48KB, x2 stages.
// ---------------------------------------------------------------------------
#define ST_AH 0
#define ST_AL 8192
#define ST_BH 16384
#define ST_BL 32768
#define ST_BYTES 49152
#define SMEM_BYTES (2 * ST_BYTES)   // 98304

__device__ __forceinline__ void load_a_sens(const float* __restrict__ xa,
                                            const float* __restrict__ xb,
                                            int m0, int k0, int tid, float* ar)
{
#pragma unroll
    for (int it = 0; it < 4; it++) {
        int idx = tid + it * 256;
        int row = idx >> 4, cg = idx & 15;
        int gm  = m0 + row;
        int kg  = k0 + cg * 4;
        int t = gm >> 9, bb = gm & 511;
        const float* src;
        if (kg < EBD) src = xa + (size_t)(bb * TSEQ + t) * EBD + kg;
        else          src = xb + (size_t)(bb * TSEQ + t) * VFD + (kg - EBD);
        float4 v = *(const float4*)src;
        ar[it * 4 + 0] = v.x; ar[it * 4 + 1] = v.y;
        ar[it * 4 + 2] = v.z; ar[it * 4 + 3] = v.w;
    }
}

template<bool SENSG, bool CFC>
__device__ void gemm_tile(const float* __restrict__ xa,   // SENSG: base
                          const float* __restrict__ xb,   // SENSG: visual
                          const char* __restrict__ apA, int KCa,  // packed A pt1
                          const char* __restrict__ apB,           // packed A pt2
                          const char* __restrict__ Wp, int KCtot,
                          int kcBeg, int kcEnd,
                          const float* __restrict__ bias,
                          const float* __restrict__ uadd,
                          char* __restrict__ outPack, int KCout,
                          float* __restrict__ outF, bool accF,
                          int N, int m0, int nbI, char* smem)
{
    const uint32_t smem_base = smem_u32(smem);

    const int tid  = threadIdx.x;
    const int wid  = tid >> 5;
    const int lane = tid & 31;
    const int wm   = wid >> 2;
    const int wn   = wid & 3;
    const int g    = lane >> 2;
    const int tg   = lane & 3;

    const int n0 = nbI * 128;
    const int mb = m0 >> 6;

    float acc[2][4][4];
#pragma unroll
    for (int a = 0; a < 2; a++)
#pragma unroll
        for (int b = 0; b < 4; b++)
#pragma unroll
            for (int c = 0; c < 4; c++) acc[a][b][c] = 0.f;

    float ar[16];
    if (SENSG) load_a_sens(xa, xb, m0, kcBeg << 6, tid, ar);

    // ---- prologue: async-copy first chunk ----
    {
        uint32_t dst = smem_base + (uint32_t)(kcBeg & 1) * ST_BYTES;
        if (!SENSG) {
            const char* ab = apA + (size_t)(mb * KCa + kcBeg) * 16384;
#pragma unroll
            for (int j = 0; j < 4; j++) {
                int i = tid + j * 256;
                CP_ASYNC16(dst + ST_AH + i * 16, ab + i * 16);
            }
        }
        const char* ws = Wp + (size_t)(nbI * KCtot + kcBeg) * 32768;
#pragma unroll
        for (int j = 0; j < 8; j++) {
            int i = tid + j * 256;
            CP_ASYNC16(dst + ST_BH + i * 16, ws + i * 16);
        }
        CP_COMMIT();
    }

    for (int ch = kcBeg; ch < kcEnd; ch++) {
        const int bsel = ch & 1;
        char* stage = smem + bsel * ST_BYTES;
        const uint32_t stage_u = smem_base + (uint32_t)bsel * ST_BYTES;

        if (SENSG) {
#pragma unroll
            for (int it = 0; it < 4; it++) {
                int idx = tid + it * 256;
                int row = idx >> 4, cg = idx & 15;
                float x0 = ar[it * 4 + 0], x1 = ar[it * 4 + 1];
                float x2 = ar[it * 4 + 2], x3 = ar[it * 4 + 3];
                __nv_bfloat16 h0 = __float2bfloat16(x0);
                __nv_bfloat16 h1 = __float2bfloat16(x1);
                __nv_bfloat16 h2 = __float2bfloat16(x2);
                __nv_bfloat16 h3 = __float2bfloat16(x3);
                __nv_bfloat16 l0 = __float2bfloat16(x0 - __bfloat162float(h0));
                __nv_bfloat16 l1 = __float2bfloat16(x1 - __bfloat162float(h1));
                __nv_bfloat16 l2 = __float2bfloat16(x2 - __bfloat162float(h2));
                __nv_bfloat16 l3 = __float2bfloat16(x3 - __bfloat162float(h3));
                uint32_t off = SWZ((uint32_t)(row * 128 + cg * 8));
                *(uint2*)(stage + ST_AH + off) = make_uint2(pack_bf2(h0, h1), pack_bf2(h2, h3));
                *(uint2*)(stage + ST_AL + off) = make_uint2(pack_bf2(l0, l1), pack_bf2(l2, l3));
            }
        }

        CP_WAIT0();
        __syncthreads();

        // ---- prefetch chunk ch+1 (overlaps MMAs below) ----
        if (ch + 1 < kcEnd) {
            uint32_t dst = smem_base + (uint32_t)((ch + 1) & 1) * ST_BYTES;
            if (!SENSG) {
                int kc = ch + 1;
                const char* ab = (kc < KCa)
                    ? apA + (size_t)(mb * KCa + kc) * 16384
                    : apB + (size_t)(mb * (kcEnd - KCa) + (kc - KCa)) * 16384;
#pragma unroll
                for (int j = 0; j < 4; j++) {
                    int i = tid + j * 256;
                    CP_ASYNC16(dst + ST_AH + i * 16, ab + i * 16);
                }
            }
            const char* ws = Wp + (size_t)(nbI * KCtot + ch + 1) * 32768;
#pragma unroll
            for (int j = 0; j < 8; j++) {
                int i = tid + j * 256;
                CP_ASYNC16(dst + ST_BH + i * 16, ws + i * 16);
            }
            CP_COMMIT();
            if (SENSG) load_a_sens(xa, xb, m0, (ch + 1) << 6, tid, ar);
        }

        // ---- MMAs: 4 k16 steps per 64-chunk ----
        const uint32_t sAh = stage_u + ST_AH;
        const uint32_t sAl = stage_u + ST_AL;
        const uint32_t sBh = stage_u + ST_BH;
        const uint32_t sBl = stage_u + ST_BL;
#pragma unroll
        for (int ks = 0; ks < 4; ks++) {
            uint32_t ah[2][4], al[2][4], bh[4][2], bl[4][2];
#pragma unroll
            for (int mt = 0; mt < 2; mt++) {
                int arow = wm * 32 + mt * 16 + (lane & 15);
                uint32_t aoff = SWZ((uint32_t)(arow * 128 + (ks * 16 + (lane >> 4) * 8) * 2));
                LDSM_X4(ah[mt][0], ah[mt][1], ah[mt][2], ah[mt][3], sAh + aoff);
                LDSM_X4(al[mt][0], al[mt][1], al[mt][2], al[mt][3], sAl + aoff);
            }
#pragma unroll
            for (int nt = 0; nt < 4; nt += 2) {
                int brow = wn * 32 + nt * 8 + ((lane >> 4) & 1) * 8 + (lane & 7);
                uint32_t boff = SWZ((uint32_t)(brow * 128 + (ks * 16 + ((lane >> 3) & 1) * 8) * 2));
                LDSM_X4(bh[nt][0], bh[nt][1], bh[nt + 1][0], bh[nt + 1][1], sBh + boff);
                LDSM_X4(bl[nt][0], bl[nt][1], bl[nt + 1][0], bl[nt + 1][1], sBl + boff);
            }
#pragma unroll
            for (int mt = 0; mt < 2; mt++)
#pragma unroll
                for (int nt = 0; nt < 4; nt++) {
                    mma16816(acc[mt][nt], ah[mt], bh[nt]);
                    mma16816(acc[mt][nt], ah[mt], bl[nt]);
                    mma16816(acc[mt][nt], al[mt], bh[nt]);
                }
        }
        __syncthreads();
    }

    // ---- epilogue ----
    if (CFC) {
        const int Hd = N >> 2;
        const int jbase = n0 >> 2;
        char* ob = outPack + (size_t)(mb * KCout + (jbase >> 6)) * 16384;
#pragma unroll
        for (int mt = 0; mt < 2; mt++) {
#pragma unroll
            for (int rh = 0; rh < 2; rh++) {
                int row = m0 + wm * 32 + mt * 16 + rh * 8 + g;
#pragma unroll
                for (int qi = 0; qi < 2; qi++) {
                    float f1  = acc[mt][2 * qi + 0][rh * 2 + 0];
                    float f2  = acc[mt][2 * qi + 0][rh * 2 + 1];
                    float tav = acc[mt][2 * qi + 1][rh * 2 + 0];
                    float tbv = acc[mt][2 * qi + 1][rh * 2 + 1];
                    int j = jbase + wn * 8 + qi * 4 + tg;
                    float4 bq = *(const float4*)(bias + 4 * j);
                    f1 += bq.x; f2 += bq.y; tav += bq.z; tbv += bq.w;
                    if (uadd != nullptr) {
                        int pc = n0 + wn * 32 + qi * 16 + tg * 2;
                        float2 u01 = *(const float2*)(uadd + (size_t)row * N + pc);
                        float2 u23 = *(const float2*)(uadd + (size_t)row * N + pc + 8);
                        f1 += u01.x; f2 += u01.y; tav += u23.x; tbv += u23.y;
                    }
                    float s = 1.f / (1.f + expf(-(tav + tbv)));
                    float h = tanhf(f1) * (1.f - s) + s * tanhf(f2);
                    __nv_bfloat16 hh = __float2bfloat16(h);
                    __nv_bfloat16 hl = __float2bfloat16(h - __bfloat162float(hh));
                    uint32_t off = SWZ((uint32_t)((row & 63) * 128 + (j & 63) * 2));
                    *(__nv_bfloat16*)(ob + off)        = hh;
                    *(__nv_bfloat16*)(ob + 8192 + off) = hl;
                    if (outF != nullptr)
                        outF[(size_t)row * Hd + j] = h;
                }
            }
        }
    } else {
#pragma unroll
        for (int mt = 0; mt < 2; mt++)
#pragma unroll
            for (int rh = 0; rh < 2; rh++) {
                int row = m0 + wm * 32 + mt * 16 + rh * 8 + g;
#pragma unroll
                for (int nt = 0; nt < 4; nt++) {
                    int col = n0 + wn * 32 + nt * 8 + tg * 2;
                    float2 v = make_float2(acc[mt][nt][rh * 2 + 0], acc[mt][nt][rh * 2 + 1]);
                    if (accF) {
                        float2 o = *(float2*)(outF + (size_t)row * N + col);
                        v.x += o.x; v.y += o.y;
                    }
                    *(float2*)(outF + (size_t)row * N + col) = v;
                }
            }
    }
}

// ---------------------------------------------------------------------------
// Head kernel: U0 slices 0 and 1 (rows 0..1023), grid (16 nb, 16 mb)
// ---------------------------------------------------------------------------
__global__ __launch_bounds__(256, 2)
void u0_head(const float* __restrict__ base, const float* __restrict__ visual)
{
    extern __shared__ char smem[];
    gemm_tile<true, false>(base, visual, nullptr, 0, nullptr,
                           (const char*)g_W0x, 12, 0, 12,
                           nullptr, nullptr, nullptr, 0,
                           g_U0, false,
                           N0, blockIdx.y * 64, blockIdx.x, smem);
}

// ---------------------------------------------------------------------------
// Fused per-step kernel. Weave plan for U0 slice t+2 (128 tiles x 12 kc):
//   phase0 (cap 8):  CTAs 128..147 -> tiles 0..19,  kc[0,8),  write
//   phase1 (cap 12): CTAs  64..147 -> tiles 20..103, kc[0,12), write
//   phase2 (cap 12): CTAs  16..35  -> tiles 0..19,  kc[8,12), accumulate
//                    CTAs  36..59  -> tiles 104..127, kc[0,12), write
// Phase caps: 8 + 12 + 12 = 32 chunk-times (was 12+12+12 = 36).
// ---------------------------------------------------------------------------
__global__ __launch_bounds__(256, 2)
void step_kernel(const float* __restrict__ base, const float* __restrict__ visual,
                 float* __restrict__ dout, int t)
{
    extern __shared__ char smem[];
    const int c = (int)blockIdx.x;
    const int tw = t + 2;
    const bool weave = (tw < TSEQ);
    float* u0w = g_U0 + (size_t)tw * BATCH * N0;

    const char* h0r = (const char*)g_h0 + (size_t)(t & 1) * (BATCH * H0 * 4);
    char*       h0w = (char*)g_h0 + (size_t)((t + 1) & 1) * (BATCH * H0 * 4);
    const char* h1r = (const char*)g_h1 + (size_t)(t & 1) * (BATCH * H1 * 4);
    char*       h1w = (char*)g_h1 + (size_t)((t + 1) & 1) * (BATCH * H1 * 4);
    const char* h2r = (const char*)g_h2 + (size_t)(t & 1) * (BATCH * H2 * 4);
    char*       h2w = (char*)g_h2 + (size_t)((t + 1) & 1) * (BATCH * H2 * 4);

    // ---- phase 0: layer 0 (128 tiles, 8 kc) + U0 tiles 0..19 kc[0,8) ----
    if (c < 128) {
        int nb = c & 15, mb = c >> 4;
        gemm_tile<false, true>(nullptr, nullptr, h0r, 8, nullptr,
                               (const char*)g_W0h, 8, 0, 8,
                               g_b0, g_U0 + (size_t)t * BATCH * N0,
                               h0w, 8, nullptr, false,
                               N0, mb * 64, nb, smem);
    } else if (weave) {
        int u = c - 128;                      // tiles 0..19
        gemm_tile<true, false>(base, visual, nullptr, 0, nullptr,
                               (const char*)g_W0x, 12, 0, 8,
                               nullptr, nullptr, nullptr, 0,
                               g_U0, false,
                               N0, tw * BATCH + (u >> 4) * 64, u & 15, smem);
    }
    grid_barrier();

    // ---- phase 1: layer 1 (64 tiles, 12 kc) + U0 tiles 20..103 full ----
    if (c < 64) {
        int nb = c & 7, mb = c >> 3;
        gemm_tile<false, true>(nullptr, nullptr, h0w, 8, h1r,
                               (const char*)g_W1, 12, 0, 12,
                               g_b1, nullptr,
                               h1w, 4, nullptr, false,
                               N1, mb * 64, nb, smem);
    } else if (weave) {
        int u = c - 64 + 20;                  // tiles 20..103
        gemm_tile<true, false>(base, visual, nullptr, 0, nullptr,
                               (const char*)g_W0x, 12, 0, 12,
                               nullptr, nullptr, nullptr, 0,
                               g_U0, false,
                               N0, tw * BATCH + (u >> 4) * 64, u & 15, smem);
    }
    grid_barrier();

    // ---- phase 2: layer 2 (16 tiles, 5 kc) + U0 tails + U0 tiles 104..127 ----
    if (c < 16) {
        int nb = c & 1, mb = c >> 1;
        float* o2 = (t == TSEQ - 1) ? dout : nullptr;
        gemm_tile<false, true>(nullptr, nullptr, h1w, 4, h2r,
                               (const char*)g_W2, 5, 0, 5,
                               g_b2, nullptr,
                               h2w, 1, o2, false,
                               N2, mb * 64, nb, smem);
    } else if (weave && c < 36) {
        int u = c - 16;                       // tiles 0..19, kc[8,12), accumulate
        gemm_tile<true, false>(base, visual, nullptr, 0, nullptr,
                               (const char*)g_W0x, 12, 8, 12,
                               nullptr, nullptr, nullptr, 0,
                               g_U0, true,
                               N0, tw * BATCH + (u >> 4) * 64, u & 15, smem);
    } else if (weave && c < 60) {
        int u = 104 + (c - 36);               // tiles 104..127 full
        gemm_tile<true, false>(base, visual, nullptr, 0, nullptr,
                               (const char*)g_W0x, 12, 0, 12,
                               nullptr, nullptr, nullptr, 0,
                               g_U0, false,
                               N0, tw * BATCH + (u >> 4) * 64, u & 15, smem);
    }
    (void)u0w;
}

// ---------------------------------------------------------------------------
// kernel_launch — launches: prep_all(1), u0_head(2), step t=0..63 (3..66).
// ncu -s 5 -c 1 therefore profiles step t=3 (a representative step).
// ---------------------------------------------------------------------------
extern "C" void kernel_launch(void* const* d_in, const int* in_sizes, int n_in,
                              void* d_out, int out_size)
{
    (void)in_sizes; (void)n_in; (void)out_size;
    const float* base   = (const float*)d_in[0];
    const float* visual = (const float*)d_in[1];

    Params pr;
    for (int l = 0; l < 3; l++) {
        int o = 2 + l * 9;
        pr.w[l][0] = (const float*)d_in[o + 0];  pr.b[l][0] = (const float*)d_in[o + 1];
        pr.w[l][1] = (const float*)d_in[o + 2];  pr.b[l][1] = (const float*)d_in[o + 3];
        pr.w[l][2] = (const float*)d_in[o + 4];  pr.b[l][2] = (const float*)d_in[o + 5];
        pr.w[l][3] = (const float*)d_in[o + 6];  pr.b[l][3] = (const float*)d_in[o + 7];
        pr.mk[l]   = (const float*)d_in[o + 8];
    }

    cudaFuncSetAttribute(u0_head,
                         cudaFuncAttributeMaxDynamicSharedMemorySize, SMEM_BYTES);
    cudaFuncSetAttribute(step_kernel,
                         cudaFuncAttributeMaxDynamicSharedMemorySize, SMEM_BYTES);

    int tot = EW + NBIAS + NZ;
    prep_all<<<(tot + 255) / 256, 256>>>(pr);

    u0_head<<<dim3(16, 16), 256, SMEM_BYTES>>>(base, visual);

    for (int t = 0; t < TSEQ; t++)
        step_kernel<<<148, 256, SMEM_BYTES>>>(base, visual, (float*)d_out, t);
}

// round 14
// speedup vs baseline: 5.1808x; 1.6443x over previous
#include <cuda_runtime.h>
#include <cuda_bf16.h>
#include <cstdint>
#include <math.h>

// ---------------------------------------------------------------------------
// Problem constants
// ---------------------------------------------------------------------------
#define TSEQ  64
#define BATCH 512
#define EBD   256
#define VFD   512
#define SENSD 768
#define H0    512
#define H1    256
#define H2    64
#define C0    1280
#define C1    768
#define C2    320
#define N0    2048         // 4*H0 physical (gate-interleaved, permuted)
#define N1    1024
#define N2    256
#define NROWS (TSEQ * BATCH)

#define E0 (C0 * H0)
#define E1 (C1 * H1)
#define E2 (C2 * H2)
#define EW (E0 + E1 + E2)
#define NBIAS 3328
#define NZ (BATCH * (H0 + H1 + H2))

// ---------------------------------------------------------------------------
// Device-global scratch.
// Weights: per (nb, kc) block = 32 KB: [hi 16KB: 128 n-rows x 64 k bf16,
//   128B rows, SW128][lo 16KB same].
// Hidden states: packed A-tiles, per (mb, kc) block = 16 KB:
//   [hi 8KB: 64 rows x 64 k bf16, SW128][lo 8KB same].
// ---------------------------------------------------------------------------
__device__ float g_W0x[SENSD * N0];   // 16 nb x 12 kc
__device__ float g_W0h[H0 * N0];      // 16 nb x  8 kc
__device__ float g_W1 [C1 * N1];      //  8 nb x 12 kc
__device__ float g_W2 [C2 * N2];      //  2 nb x  5 kc
__device__ float g_b0 [N0];
__device__ float g_b1 [N1];
__device__ float g_b2 [N2];
__device__ float g_U0 [(size_t)NROWS * N0];
__device__ float g_h0 [2 * BATCH * H0];   // packed 2 x (8 mb x 8 kc x 16KB)
__device__ float g_h1 [2 * BATCH * H1];   // packed 2 x (8 mb x 4 kc x 16KB)
__device__ float g_h2 [2 * BATCH * H2];   // packed 2 x (8 mb x 1 kc x 16KB)

// ---------------------------------------------------------------------------
// Helpers (portable PTX only: mma.sync / ldmatrix / cp.async)
// ---------------------------------------------------------------------------
__device__ __forceinline__ uint32_t smem_u32(const void* p) {
    uint32_t a;
    asm("{ .reg .u64 t; cvta.to.shared.u64 t, %1; cvt.u32.u64 %0, t; }" : "=r"(a) : "l"(p));
    return a;
}
#define SWZ(o) ((o) ^ (((o) >> 3) & 0x70))

#define LDSM_X4(r0, r1, r2, r3, a) \
    asm volatile("ldmatrix.sync.aligned.m8n8.x4.shared.b16 {%0,%1,%2,%3}, [%4];" \
                 : "=r"(r0), "=r"(r1), "=r"(r2), "=r"(r3) : "r"(a))

__device__ __forceinline__ void mma16816(float (&d)[4], const uint32_t (&a)[4],
                                         const uint32_t (&b)[2]) {
    asm volatile(
        "mma.sync.aligned.m16n8k16.row.col.f32.bf16.bf16.f32 "
        "{%0,%1,%2,%3}, {%4,%5,%6,%7}, {%8,%9}, {%0,%1,%2,%3};"
        : "+f"(d[0]), "+f"(d[1]), "+f"(d[2]), "+f"(d[3])
        : "r"(a[0]), "r"(a[1]), "r"(a[2]), "r"(a[3]), "r"(b[0]), "r"(b[1]));
}

#define CP_ASYNC16(dst, src) \
    asm volatile("cp.async.cg.shared.global [%0], [%1], 16;" :: "r"(dst), "l"(src))
#define CP_COMMIT() asm volatile("cp.async.commit_group;" ::: "memory")
#define CP_WAIT0()  asm volatile("cp.async.wait_group 0;" ::: "memory")

__device__ __forceinline__ uint32_t pack_bf2(__nv_bfloat16 a, __nv_bfloat16 b) {
    uint16_t ua = *(uint16_t*)&a, ub = *(uint16_t*)&b;
    return (uint32_t)ua | ((uint32_t)ub << 16);
}

__host__ __device__ __forceinline__ int perm_col(int n) {
    int grp = n >> 5, L = n & 31, Q = L >> 2, r = L & 3;
    int pl = ((Q & 3) << 1) + (r & 1) + (((Q >> 2) << 1) + (r >> 1)) * 8;
    return (grp << 5) + pl;
}

// ---------------------------------------------------------------------------
// Merged prep kernel: all weights + biases + zero hidden states.
// ---------------------------------------------------------------------------
struct Params {
    const float* w[3][4];
    const float* b[3][4];
    const float* mk[3];
};

__global__ void prep_all(Params pr)
{
    int idx = blockIdx.x * blockDim.x + threadIdx.x;
    if (idx < EW) {
        int l, i, C, H;
        if (idx < E0)            { l = 0; i = idx;           C = C0; H = H0; }
        else if (idx < E0 + E1)  { l = 1; i = idx - E0;      C = C1; H = H1; }
        else                     { l = 2; i = idx - E0 - E1; C = C2; H = H2; }
        int k = i / H, j = i - k * H;
        float mkv = pr.mk[l][(size_t)j * C + k];
        float v[4];
#pragma unroll
        for (int q = 0; q < 4; q++) v[q] = pr.w[l][q][(size_t)j * C + k];
        v[0] *= mkv; v[1] *= mkv;

        char* bas; int KC, kk;
        if (l == 0) {
            if (k < SENSD) { bas = (char*)g_W0x; KC = 12; kk = k; }
            else           { bas = (char*)g_W0h; KC = 8;  kk = k - SENSD; }
        } else if (l == 1) { bas = (char*)g_W1; KC = 12; kk = k; }
        else               { bas = (char*)g_W2; KC = 5;  kk = k; }
        int kc = kk >> 6, kr = kk & 63;
#pragma unroll
        for (int q = 0; q < 4; q++) {
            int P  = perm_col(4 * j + q);
            int nb = P >> 7, nr = P & 127;
            size_t blk = (size_t)(nb * KC + kc) * 32768;
            uint32_t off = SWZ((uint32_t)(nr * 128 + kr * 2));
            float x = v[q];
            __nv_bfloat16 h = __float2bfloat16(x);
            __nv_bfloat16 lo = __float2bfloat16(x - __bfloat162float(h));
            *(__nv_bfloat16*)(bas + blk + off)         = h;
            *(__nv_bfloat16*)(bas + blk + 16384 + off) = lo;
        }
        return;
    }
    if (idx < EW + NBIAS) {
        int c = idx - EW;
        float* bo; const float* b; int j, q;
        if (c < 2048)      { q = c & 3; j = c >> 2; bo = g_b0 + c; b = pr.b[0][q]; }
        else if (c < 3072) { int cc = c - 2048; q = cc & 3; j = cc >> 2; bo = g_b1 + cc; b = pr.b[1][q]; }
        else               { int cc = c - 3072; q = cc & 3; j = cc >> 2; bo = g_b2 + cc; b = pr.b[2][q]; }
        *bo = b[j];
        return;
    }
    int z = idx - EW - NBIAS;
    if (z < NZ) {
        if (z < BATCH * H0)             g_h0[z] = 0.f;
        else if (z < BATCH * (H0 + H1)) g_h1[z - BATCH * H0] = 0.f;
        else                            g_h2[z - BATCH * (H0 + H1)] = 0.f;
    }
}

// ---------------------------------------------------------------------------
// Split-bf16 HMMA GEMM tile (+ optional fused CfC epilogue).
// Tile 64(M) x 128(N), 8 warps (2M x 4N), K-chunks of 64, double-buffered.
//   SENSG=true : A = sensory fp32, converted in-loop; supports kc sub-range
//   SENSG=false: A = packed split-bf16 tiles (hidden states), cp.async'd
// Stage: AH 8K | AL 8K | BH 16K | BL 16K = 48KB, x2 stages.
// ---------------------------------------------------------------------------
#define ST_AH 0
#define ST_AL 8192
#define ST_BH 16384
#define ST_BL 32768
#define ST_BYTES 49152
#define SMEM_BYTES (2 * ST_BYTES)   // 98304

__device__ __forceinline__ void load_a_sens(const float* __restrict__ xa,
                                            const float* __restrict__ xb,
                                            int m0, int k0, int tid, float* ar)
{
#pragma unroll
    for (int it = 0; it < 4; it++) {
        int idx = tid + it * 256;
        int row = idx >> 4, cg = idx & 15;
        int gm  = m0 + row;
        int kg  = k0 + cg * 4;
        int t = gm >> 9, bb = gm & 511;
        const float* src;
        if (kg < EBD) src = xa + (size_t)(bb * TSEQ + t) * EBD + kg;
        else          src = xb + (size_t)(bb * TSEQ + t) * VFD + (kg - EBD);
        float4 v = *(const float4*)src;
        ar[it * 4 + 0] = v.x; ar[it * 4 + 1] = v.y;
        ar[it * 4 + 2] = v.z; ar[it * 4 + 3] = v.w;
    }
}

template<bool SENSG, bool CFC>
__device__ void gemm_tile(const float* __restrict__ xa,   // SENSG: base
                          const float* __restrict__ xb,   // SENSG: visual
                          const char* __restrict__ apA, int KCa,  // packed A pt1
                          const char* __restrict__ apB,           // packed A pt2
                          const char* __restrict__ Wp, int KCtot,
                          int kcBeg, int kcEnd,
                          const float* __restrict__ bias,
                          const float* __restrict__ uadd,
                          char* __restrict__ outPack, int KCout,
                          float* __restrict__ outF, bool accF,
                          int N, int m0, int nbI, char* smem)
{
    const uint32_t smem_base = smem_u32(smem);

    const int tid  = threadIdx.x;
    const int wid  = tid >> 5;
    const int lane = tid & 31;
    const int wm   = wid >> 2;
    const int wn   = wid & 3;
    const int g    = lane >> 2;
    const int tg   = lane & 3;

    const int n0 = nbI * 128;
    const int mb = m0 >> 6;

    float acc[2][4][4];
#pragma unroll
    for (int a = 0; a < 2; a++)
#pragma unroll
        for (int b = 0; b < 4; b++)
#pragma unroll
            for (int c = 0; c < 4; c++) acc[a][b][c] = 0.f;

    float ar[16];
    if (SENSG) load_a_sens(xa, xb, m0, kcBeg << 6, tid, ar);

    // ---- prologue: async-copy first chunk ----
    {
        uint32_t dst = smem_base + (uint32_t)(kcBeg & 1) * ST_BYTES;
        if (!SENSG) {
            const char* ab = apA + (size_t)(mb * KCa + kcBeg) * 16384;
#pragma unroll
            for (int j = 0; j < 4; j++) {
                int i = tid + j * 256;
                CP_ASYNC16(dst + ST_AH + i * 16, ab + i * 16);
            }
        }
        const char* ws = Wp + (size_t)(nbI * KCtot + kcBeg) * 32768;
#pragma unroll
        for (int j = 0; j < 8; j++) {
            int i = tid + j * 256;
            CP_ASYNC16(dst + ST_BH + i * 16, ws + i * 16);
        }
        CP_COMMIT();
    }

    for (int ch = kcBeg; ch < kcEnd; ch++) {
        const int bsel = ch & 1;
        char* stage = smem + bsel * ST_BYTES;
        const uint32_t stage_u = smem_base + (uint32_t)bsel * ST_BYTES;

        if (SENSG) {
#pragma unroll
            for (int it = 0; it < 4; it++) {
                int idx = tid + it * 256;
                int row = idx >> 4, cg = idx & 15;
                float x0 = ar[it * 4 + 0], x1 = ar[it * 4 + 1];
                float x2 = ar[it * 4 + 2], x3 = ar[it * 4 + 3];
                __nv_bfloat16 h0 = __float2bfloat16(x0);
                __nv_bfloat16 h1 = __float2bfloat16(x1);
                __nv_bfloat16 h2 = __float2bfloat16(x2);
                __nv_bfloat16 h3 = __float2bfloat16(x3);
                __nv_bfloat16 l0 = __float2bfloat16(x0 - __bfloat162float(h0));
                __nv_bfloat16 l1 = __float2bfloat16(x1 - __bfloat162float(h1));
                __nv_bfloat16 l2 = __float2bfloat16(x2 - __bfloat162float(h2));
                __nv_bfloat16 l3 = __float2bfloat16(x3 - __bfloat162float(h3));
                uint32_t off = SWZ((uint32_t)(row * 128 + cg * 8));
                *(uint2*)(stage + ST_AH + off) = make_uint2(pack_bf2(h0, h1), pack_bf2(h2, h3));
                *(uint2*)(stage + ST_AL + off) = make_uint2(pack_bf2(l0, l1), pack_bf2(l2, l3));
            }
        }

        CP_WAIT0();
        __syncthreads();

        // ---- prefetch chunk ch+1 (overlaps MMAs below) ----
        if (ch + 1 < kcEnd) {
            uint32_t dst = smem_base + (uint32_t)((ch + 1) & 1) * ST_BYTES;
            if (!SENSG) {
                int kc = ch + 1;
                const char* ab = (kc < KCa)
                    ? apA + (size_t)(mb * KCa + kc) * 16384
                    : apB + (size_t)(mb * (kcEnd - KCa) + (kc - KCa)) * 16384;
#pragma unroll
                for (int j = 0; j < 4; j++) {
                    int i = tid + j * 256;
                    CP_ASYNC16(dst + ST_AH + i * 16, ab + i * 16);
                }
            }
            const char* ws = Wp + (size_t)(nbI * KCtot + ch + 1) * 32768;
#pragma unroll
            for (int j = 0; j < 8; j++) {
                int i = tid + j * 256;
                CP_ASYNC16(dst + ST_BH + i * 16, ws + i * 16);
            }
            CP_COMMIT();
            if (SENSG) load_a_sens(xa, xb, m0, (ch + 1) << 6, tid, ar);
        }

        // ---- MMAs: 4 k16 steps per 64-chunk ----
        const uint32_t sAh = stage_u + ST_AH;
        const uint32_t sAl = stage_u + ST_AL;
        const uint32_t sBh = stage_u + ST_BH;
        const uint32_t sBl = stage_u + ST_BL;
#pragma unroll
        for (int ks = 0; ks < 4; ks++) {
            uint32_t ah[2][4], al[2][4], bh[4][2], bl[4][2];
#pragma unroll
            for (int mt = 0; mt < 2; mt++) {
                int arow = wm * 32 + mt * 16 + (lane & 15);
                uint32_t aoff = SWZ((uint32_t)(arow * 128 + (ks * 16 + (lane >> 4) * 8) * 2));
                LDSM_X4(ah[mt][0], ah[mt][1], ah[mt][2], ah[mt][3], sAh + aoff);
                LDSM_X4(al[mt][0], al[mt][1], al[mt][2], al[mt][3], sAl + aoff);
            }
#pragma unroll
            for (int nt = 0; nt < 4; nt += 2) {
                int brow = wn * 32 + nt * 8 + ((lane >> 4) & 1) * 8 + (lane & 7);
                uint32_t boff = SWZ((uint32_t)(brow * 128 + (ks * 16 + ((lane >> 3) & 1) * 8) * 2));
                LDSM_X4(bh[nt][0], bh[nt][1], bh[nt + 1][0], bh[nt + 1][1], sBh + boff);
                LDSM_X4(bl[nt][0], bl[nt][1], bl[nt + 1][0], bl[nt + 1][1], sBl + boff);
            }
#pragma unroll
            for (int mt = 0; mt < 2; mt++)
#pragma unroll
                for (int nt = 0; nt < 4; nt++) {
                    mma16816(acc[mt][nt], ah[mt], bh[nt]);
                    mma16816(acc[mt][nt], ah[mt], bl[nt]);
                    mma16816(acc[mt][nt], al[mt], bh[nt]);
                }
        }
        __syncthreads();
    }

    // ---- epilogue ----
    if (CFC) {
        const int Hd = N >> 2;
        const int jbase = n0 >> 2;
        char* ob = outPack + (size_t)(mb * KCout + (jbase >> 6)) * 16384;
#pragma unroll
        for (int mt = 0; mt < 2; mt++) {
#pragma unroll
            for (int rh = 0; rh < 2; rh++) {
                int row = m0 + wm * 32 + mt * 16 + rh * 8 + g;
#pragma unroll
                for (int qi = 0; qi < 2; qi++) {
                    float f1  = acc[mt][2 * qi + 0][rh * 2 + 0];
                    float f2  = acc[mt][2 * qi + 0][rh * 2 + 1];
                    float tav = acc[mt][2 * qi + 1][rh * 2 + 0];
                    float tbv = acc[mt][2 * qi + 1][rh * 2 + 1];
                    int j = jbase + wn * 8 + qi * 4 + tg;
                    float4 bq = *(const float4*)(bias + 4 * j);
                    f1 += bq.x; f2 += bq.y; tav += bq.z; tbv += bq.w;
                    if (uadd != nullptr) {
                        int pc = n0 + wn * 32 + qi * 16 + tg * 2;
                        float2 u01 = *(const float2*)(uadd + (size_t)row * N + pc);
                        float2 u23 = *(const float2*)(uadd + (size_t)row * N + pc + 8);
                        f1 += u01.x; f2 += u01.y; tav += u23.x; tbv += u23.y;
                    }
                    float s = 1.f / (1.f + expf(-(tav + tbv)));
                    float h = tanhf(f1) * (1.f - s) + s * tanhf(f2);
                    __nv_bfloat16 hh = __float2bfloat16(h);
                    __nv_bfloat16 hl = __float2bfloat16(h - __bfloat162float(hh));
                    uint32_t off = SWZ((uint32_t)((row & 63) * 128 + (j & 63) * 2));
                    *(__nv_bfloat16*)(ob + off)        = hh;
                    *(__nv_bfloat16*)(ob + 8192 + off) = hl;
                    if (outF != nullptr)
                        outF[(size_t)row * Hd + j] = h;
                }
            }
        }
    } else {
#pragma unroll
        for (int mt = 0; mt < 2; mt++)
#pragma unroll
            for (int rh = 0; rh < 2; rh++) {
                int row = m0 + wm * 32 + mt * 16 + rh * 8 + g;
#pragma unroll
                for (int nt = 0; nt < 4; nt++) {
                    int col = n0 + wn * 32 + nt * 8 + tg * 2;
                    float2 v = make_float2(acc[mt][nt][rh * 2 + 0], acc[mt][nt][rh * 2 + 1]);
                    if (accF) {
                        float2 o = *(float2*)(outF + (size_t)row * N + col);
                        v.x += o.x; v.y += o.y;
                    }
                    *(float2*)(outF + (size_t)row * N + col) = v;
                }
            }
    }
}

// ---------------------------------------------------------------------------
// Head kernel: U0 slices 0..3 (rows 0..2047), grid (16 nb, 32 mb)
// ---------------------------------------------------------------------------
__global__ __launch_bounds__(256, 2)
void u0_head(const float* __restrict__ base, const float* __restrict__ visual)
{
    extern __shared__ char smem[];
    gemm_tile<true, false>(base, visual, nullptr, 0, nullptr,
                           (const char*)g_W0x, 12, 0, 12,
                           nullptr, nullptr, nullptr, 0,
                           g_U0, false,
                           N0, blockIdx.y * 64, blockIdx.x, smem);
}

// ---------------------------------------------------------------------------
// Pipelined interval kernel. Interval i runs CONCURRENTLY (no barriers;
// kernel launch boundary = interval sync):
//   CTAs   0..127 : L0(t=i)      [8 ch] + one 4-chunk U0 weave segment
//   CTAs 128..191 : L1(t=i-1)    [12 ch]
//   CTAs 192..207 : L2(t=i-2)    [5 ch]   (t=63 -> also writes dout)
//   CTAs 208..295 : U0 weave slice i+2, tiles 0..87, full 12 ch
// U0 weave schedule (slice s, tiles 88..127 split over 3 intervals):
//   i=s-4: kc[0,4) write | i=s-3: kc[4,8) accum | i=s-2: kc[8,12) accum
// Slices 0..3 precomputed by u0_head. All races separated by launch bounds.
// ---------------------------------------------------------------------------
__global__ __launch_bounds__(256, 2)
void interval_kernel(const float* __restrict__ base, const float* __restrict__ visual,
                     float* __restrict__ dout, int i)
{
    extern __shared__ char smem[];
    const int c = (int)blockIdx.x;

    if (c < 128) {
        // ---- L0(t=i) ----
        if (i < TSEQ) {
            const char* h0r = (const char*)g_h0 + (size_t)(i & 1) * (BATCH * H0 * 4);
            char*       h0w = (char*)g_h0 + (size_t)((i + 1) & 1) * (BATCH * H0 * 4);
            gemm_tile<false, true>(nullptr, nullptr, h0r, 8, nullptr,
                                   (const char*)g_W0h, 8, 0, 8,
                                   g_b0, g_U0 + (size_t)i * BATCH * N0,
                                   h0w, 8, nullptr, false,
                                   N0, (c >> 4) * 64, c & 15, smem);
        }
        // ---- weave segment (4 chunks) for tiles 88..127 ----
        int s = -1, kb = 0, ke = 0, tile = 0; bool accum = false;
        if (c < 40)       { s = i + 4; kb = 0; ke = 4;  accum = false; tile = 88 + c; }
        else if (c < 80)  { s = i + 3; kb = 4; ke = 8;  accum = true;  tile = 88 + (c - 40); }
        else if (c < 120) { s = i + 2; kb = 8; ke = 12; accum = true;  tile = 88 + (c - 80); }
        if (s >= 4 && s < TSEQ) {
            gemm_tile<true, false>(base, visual, nullptr, 0, nullptr,
                                   (const char*)g_W0x, 12, kb, ke,
                                   nullptr, nullptr, nullptr, 0,
                                   g_U0, accum,
                                   N0, s * BATCH + (tile >> 4) * 64, tile & 15, smem);
        }
    } else if (c < 192) {
        // ---- L1(t=i-1) ----
        int t = i - 1;
        if (t >= 0 && t < TSEQ) {
            const char* h0w = (const char*)g_h0 + (size_t)((t + 1) & 1) * (BATCH * H0 * 4);
            const char* h1r = (const char*)g_h1 + (size_t)(t & 1) * (BATCH * H1 * 4);
            char*       h1w = (char*)g_h1 + (size_t)((t + 1) & 1) * (BATCH * H1 * 4);
            int cc = c - 128;
            gemm_tile<false, true>(nullptr, nullptr, h0w, 8, h1r,
                                   (const char*)g_W1, 12, 0, 12,
                                   g_b1, nullptr,
                                   h1w, 4, nullptr, false,
                                   N1, (cc >> 3) * 64, cc & 7, smem);
        }
    } else if (c < 208) {
        // ---- L2(t=i-2) ----
        int t = i - 2;
        if (t >= 0 && t < TSEQ) {
            const char* h1w = (const char*)g_h1 + (size_t)((t + 1) & 1) * (BATCH * H1 * 4);
            const char* h2r = (const char*)g_h2 + (size_t)(t & 1) * (BATCH * H2 * 4);
            char*       h2w = (char*)g_h2 + (size_t)((t + 1) & 1) * (BATCH * H2 * 4);
            int cc = c - 192;
            float* o2 = (t == TSEQ - 1) ? dout : nullptr;
            gemm_tile<false, true>(nullptr, nullptr, h1w, 4, h2r,
                                   (const char*)g_W2, 5, 0, 5,
                                   g_b2, nullptr,
                                   h2w, 1, o2, false,
                                   N2, (cc >> 1) * 64, cc & 1, smem);
        }
    } else {
        // ---- weave full tiles 0..87 of slice i+2 ----
        int s = i + 2;
        int tile = c - 208;   // 0..87
        if (s >= 4 && s < TSEQ) {
            gemm_tile<true, false>(base, visual, nullptr, 0, nullptr,
                                   (const char*)g_W0x, 12, 0, 12,
                                   nullptr, nullptr, nullptr, 0,
                                   g_U0, false,
                                   N0, s * BATCH + (tile >> 4) * 64, tile & 15, smem);
        }
    }
}

// ---------------------------------------------------------------------------
// kernel_launch — prep_all(1), u0_head(2), intervals 0..65 (3..68).
// ncu -s 5 -c 1 profiles interval i=3 (fully representative).
// ---------------------------------------------------------------------------
extern "C" void kernel_launch(void* const* d_in, const int* in_sizes, int n_in,
                              void* d_out, int out_size)
{
    (void)in_sizes; (void)n_in; (void)out_size;
    const float* base   = (const float*)d_in[0];
    const float* visual = (const float*)d_in[1];

    Params pr;
    for (int l = 0; l < 3; l++) {
        int o = 2 + l * 9;
        pr.w[l][0] = (const float*)d_in[o + 0];  pr.b[l][0] = (const float*)d_in[o + 1];
        pr.w[l][1] = (const float*)d_in[o + 2];  pr.b[l][1] = (const float*)d_in[o + 3];
        pr.w[l][2] = (const float*)d_in[o + 4];  pr.b[l][2] = (const float*)d_in[o + 5];
        pr.w[l][3] = (const float*)d_in[o + 6];  pr.b[l][3] = (const float*)d_in[o + 7];
        pr.mk[l]   = (const float*)d_in[o + 8];
    }

    cudaFuncSetAttribute(u0_head,
                         cudaFuncAttributeMaxDynamicSharedMemorySize, SMEM_BYTES);
    cudaFuncSetAttribute(interval_kernel,
                         cudaFuncAttributeMaxDynamicSharedMemorySize, SMEM_BYTES);

    int tot = EW + NBIAS + NZ;
    prep_all<<<(tot + 255) / 256, 256>>>(pr);

    // U0 slices 0..3
    u0_head<<<dim3(16, 32), 256, SMEM_BYTES>>>(base, visual);

    // pipelined intervals: L0(i) || L1(i-1) || L2(i-2) || U0-weave(i+2..i+4)
    for (int i = 0; i < TSEQ + 2; i++)
        interval_kernel<<<296, 256, SMEM_BYTES>>>(base, visual, (float*)d_out, i);
}